// round 2
// baseline (speedup 1.0000x reference)
#include <cuda_runtime.h>
#include <cstdint>

#define Nn 50000
#define Ee 800000
#define Dd 128
#define LN_EPS 1e-5f

// -------- scratch (static device globals; no allocations allowed) --------
__device__ __align__(16) float g_PQ[(size_t)Nn * 256];   // [P | Q] per node
__device__ __align__(16) float g_agg[(size_t)Nn * 128];  // segment_sum(m_ij, dst)
__device__ __align__(16) float g_G[(size_t)Nn * 128];    // phi_h hidden
__device__ float g_num[Nn * 3];
__device__ float g_cnt[Nn];
__device__ int   g_is64;

__device__ __forceinline__ float silu_f(float v) { return v / (1.f + __expf(-v)); }

__device__ __forceinline__ int eidx(const void* p, long long i) {
    if (g_is64) return (int)((const long long*)p)[i];
    return ((const int*)p)[i];
}

__device__ __forceinline__ void red4(float* p, float a, float b, float c, float d) {
    asm volatile("red.global.add.v4.f32 [%0], {%1,%2,%3,%4};"
                 :: "l"(p), "f"(a), "f"(b), "f"(c), "f"(d) : "memory");
}

// -------- kernel 0: zero scratch + dtype detect --------
__global__ void k_zero(const void* __restrict__ ei) {
    if (blockIdx.x == 0 && threadIdx.x == 0) {
        const int* w = (const int*)ei;
        int all0 = 1;
        #pragma unroll 1
        for (int i = 0; i < 64; i++) if (w[2 * i + 1] != 0) all0 = 0;
        g_is64 = all0;   // int64 indices: every high word is 0 (values < 2^31)
    }
    size_t i = (size_t)blockIdx.x * blockDim.x + threadIdx.x;
    size_t stride = (size_t)gridDim.x * blockDim.x;
    for (size_t j = i; j < (size_t)Nn * 128; j += stride) g_agg[j] = 0.f;
    for (size_t j = i; j < (size_t)Nn * 3;   j += stride) g_num[j] = 0.f;
    for (size_t j = i; j < (size_t)Nn;       j += stride) g_cnt[j] = 0.f;
}

// -------- kernel 1: [P|Q] = h @ We1[0:128] , h @ We1[128:256] --------
// grid (ceil(N/64), 2); blockIdx.y selects which 128-row half of We1.
__global__ __launch_bounds__(256, 2) void k_nodeprep(const float* __restrict__ h,
                                                     const float* __restrict__ We1) {
    extern __shared__ float sm[];
    float* sB = sm;            // 128*128
    float* sA = sm + 16384;    // 64*129
    const int half = blockIdx.y;
    const float* Wb = We1 + (size_t)half * 16384;
    const int row0 = blockIdx.x * 64;
    const int tid = threadIdx.x;

    for (int i = tid; i < 4096; i += 256)
        ((float4*)sB)[i] = ((const float4*)Wb)[i];
    for (int i = tid; i < 64 * 32; i += 256) {
        int r = i >> 5, c4 = i & 31;
        float4 v = make_float4(0.f, 0.f, 0.f, 0.f);
        if (row0 + r < Nn) v = *((const float4*)(h + (size_t)(row0 + r) * 128 + c4 * 4));
        float* dp = sA + r * 129 + c4 * 4;
        dp[0] = v.x; dp[1] = v.y; dp[2] = v.z; dp[3] = v.w;
    }
    __syncthreads();

    const int tx = tid & 15, ty = tid >> 4;
    const int r0 = ty * 4, c0 = tx * 8;
    float acc[4][8] = {};
    #pragma unroll 4
    for (int k = 0; k < 128; k++) {
        float a[4];
        #pragma unroll
        for (int i = 0; i < 4; i++) a[i] = sA[(r0 + i) * 129 + k];
        float4 b0 = *(float4*)(sB + k * 128 + c0);
        float4 b1 = *(float4*)(sB + k * 128 + c0 + 4);
        #pragma unroll
        for (int i = 0; i < 4; i++) {
            acc[i][0] = fmaf(a[i], b0.x, acc[i][0]);
            acc[i][1] = fmaf(a[i], b0.y, acc[i][1]);
            acc[i][2] = fmaf(a[i], b0.z, acc[i][2]);
            acc[i][3] = fmaf(a[i], b0.w, acc[i][3]);
            acc[i][4] = fmaf(a[i], b1.x, acc[i][4]);
            acc[i][5] = fmaf(a[i], b1.y, acc[i][5]);
            acc[i][6] = fmaf(a[i], b1.z, acc[i][6]);
            acc[i][7] = fmaf(a[i], b1.w, acc[i][7]);
        }
    }
    #pragma unroll
    for (int i = 0; i < 4; i++) {
        int gr = row0 + r0 + i;
        if (gr < Nn) {
            float* o = g_PQ + (size_t)gr * 256 + half * 128 + c0;
            *(float4*)o       = make_float4(acc[i][0], acc[i][1], acc[i][2], acc[i][3]);
            *(float4*)(o + 4) = make_float4(acc[i][4], acc[i][5], acc[i][6], acc[i][7]);
        }
    }
}

// -------- kernel 2: fused edge pipeline (128 edges / CTA) --------
// smem float offsets
#define EO_W    0        // 16384
#define EO_A    16384    // 128*129 = 16512
#define EO_W1G  32896    // 11*128 = 1408
#define EO_BE1  34304
#define EO_BE2  34432
#define EO_BX1  34560
#define EO_WX2  34688
#define EO_GEOM 34816    // 128*12
#define EO_REL  36352    // 128*4
#define EO_SRC  36864    // 128 ints
#define EO_DST  36992    // 128 ints
#define EO_TOT  37120    // floats -> 148480 bytes

__global__ __launch_bounds__(256, 1) void k_edge(
    const float* __restrict__ x, const float* __restrict__ vel,
    const void* __restrict__ ei,
    const float* __restrict__ We1, const float* __restrict__ be1,
    const float* __restrict__ We2, const float* __restrict__ be2,
    const float* __restrict__ Wx1, const float* __restrict__ bx1,
    const float* __restrict__ Wx2, const float* __restrict__ bx2,
    float* __restrict__ m_out)
{
    extern __shared__ float sm[];
    float* sW    = sm + EO_W;
    float* sA    = sm + EO_A;
    float* sW1g  = sm + EO_W1G;
    float* sbe1  = sm + EO_BE1;
    float* sbe2  = sm + EO_BE2;
    float* sbx1  = sm + EO_BX1;
    float* swx2  = sm + EO_WX2;
    float* sGeom = sm + EO_GEOM;  // stride 12
    float* sRel  = sm + EO_REL;   // stride 4
    int*   sSrc  = (int*)(sm + EO_SRC);
    int*   sDst  = (int*)(sm + EO_DST);

    const int tid = threadIdx.x;
    const long long e0 = (long long)blockIdx.x * 128;
    const float bx2v = bx2[0];

    // cooperative loads
    for (int i = tid; i < 4096; i += 256)
        ((float4*)sW)[i] = ((const float4*)We2)[i];
    for (int i = tid; i < 1408; i += 256) sW1g[i] = We1[256 * 128 + i];
    if (tid < 128) { sbe1[tid] = be1[tid]; sbe2[tid] = be2[tid];
                     sbx1[tid] = bx1[tid]; swx2[tid] = Wx2[tid]; }

    // geometry features, one edge per thread (tid<128)
    if (tid < 128) {
        int e = tid;
        int s = eidx(ei, e0 + e), d = eidx(ei, (long long)Ee + e0 + e);
        sSrc[e] = s; sDst[e] = d;
        float rx = x[s * 3 + 0] - x[d * 3 + 0];
        float ry = x[s * 3 + 1] - x[d * 3 + 1];
        float rz = x[s * 3 + 2] - x[d * 3 + 2];
        float d2 = rx * rx + ry * ry + rz * rz;
        float dist = fmaxf(sqrtf(d2), 1e-8f);
        float inv = 1.f / dist;
        float hx = rx * inv, hy = ry * inv, hz = rz * inv;
        sRel[e * 4 + 0] = rx; sRel[e * 4 + 1] = ry; sRel[e * 4 + 2] = rz;
        sGeom[e * 12 + 0] = d2;
        #pragma unroll
        for (int i = 0; i < 5; i++) {
            const float* vs = vel + ((size_t)s * 5 + i) * 3;
            sGeom[e * 12 + 1 + i] = vs[0] * hx + vs[1] * hy + vs[2] * hz;
        }
        #pragma unroll
        for (int i = 0; i < 5; i++) {
            const float* vd = vel + ((size_t)d * 5 + i) * 3;
            sGeom[e * 12 + 6 + i] = vd[0] * hx + vd[1] * hy + vd[2] * hz;
        }
    }
    __syncthreads();

    const int tx = tid & 15, ty = tid >> 4;
    const int r0 = ty * 8, c0 = tx * 8;

    // build t = silu(P[src]+Q[dst]+geom@We1g+be1) into sA
    #pragma unroll
    for (int rr = 0; rr < 8; rr++) {
        int e = r0 + rr;
        int s = sSrc[e], d = sDst[e];
        const float* prow = g_PQ + (size_t)s * 256 + c0;
        const float* qrow = g_PQ + (size_t)d * 256 + 128 + c0;
        float4 p0 = *(const float4*)prow,       p1 = *(const float4*)(prow + 4);
        float4 q0 = *(const float4*)qrow,       q1 = *(const float4*)(qrow + 4);
        float t[8];
        t[0] = p0.x + q0.x; t[1] = p0.y + q0.y; t[2] = p0.z + q0.z; t[3] = p0.w + q0.w;
        t[4] = p1.x + q1.x; t[5] = p1.y + q1.y; t[6] = p1.z + q1.z; t[7] = p1.w + q1.w;
        #pragma unroll
        for (int j = 0; j < 8; j++) t[j] += sbe1[c0 + j];
        #pragma unroll
        for (int g = 0; g < 11; g++) {
            float gv = sGeom[e * 12 + g];
            #pragma unroll
            for (int j = 0; j < 8; j++) t[j] = fmaf(gv, sW1g[g * 128 + c0 + j], t[j]);
        }
        #pragma unroll
        for (int j = 0; j < 8; j++) sA[e * 129 + c0 + j] = silu_f(t[j]);
    }
    __syncthreads();

    // GEMM1: acc = t @ We2
    float acc[8][8] = {};
    #pragma unroll 4
    for (int k = 0; k < 128; k++) {
        float a[8];
        #pragma unroll
        for (int i = 0; i < 8; i++) a[i] = sA[(r0 + i) * 129 + k];
        float4 b0 = *(float4*)(sW + k * 128 + c0);
        float4 b1 = *(float4*)(sW + k * 128 + c0 + 4);
        #pragma unroll
        for (int i = 0; i < 8; i++) {
            acc[i][0] = fmaf(a[i], b0.x, acc[i][0]);
            acc[i][1] = fmaf(a[i], b0.y, acc[i][1]);
            acc[i][2] = fmaf(a[i], b0.z, acc[i][2]);
            acc[i][3] = fmaf(a[i], b0.w, acc[i][3]);
            acc[i][4] = fmaf(a[i], b1.x, acc[i][4]);
            acc[i][5] = fmaf(a[i], b1.y, acc[i][5]);
            acc[i][6] = fmaf(a[i], b1.z, acc[i][6]);
            acc[i][7] = fmaf(a[i], b1.w, acc[i][7]);
        }
    }
    __syncthreads();  // all reads of sA(t), sW(We2) complete

    // m = silu(acc + be2): to shared (for GEMM2), gmem output, and agg scatter
    #pragma unroll
    for (int i = 0; i < 8; i++) {
        int e = r0 + i;
        float m8[8];
        #pragma unroll
        for (int j = 0; j < 8; j++) m8[j] = silu_f(acc[i][j] + sbe2[c0 + j]);
        #pragma unroll
        for (int j = 0; j < 8; j++) sA[e * 129 + c0 + j] = m8[j];
        float* go = m_out + (size_t)(e0 + e) * 128 + c0;
        *(float4*)go       = make_float4(m8[0], m8[1], m8[2], m8[3]);
        *(float4*)(go + 4) = make_float4(m8[4], m8[5], m8[6], m8[7]);
        float* ga = g_agg + (size_t)sDst[e] * 128 + c0;
        red4(ga,     m8[0], m8[1], m8[2], m8[3]);
        red4(ga + 4, m8[4], m8[5], m8[6], m8[7]);
    }
    // load Wx1
    for (int i = tid; i < 4096; i += 256)
        ((float4*)sW)[i] = ((const float4*)Wx1)[i];
    __syncthreads();

    // GEMM2: acc = m @ Wx1
    #pragma unroll
    for (int i = 0; i < 8; i++)
        #pragma unroll
        for (int j = 0; j < 8; j++) acc[i][j] = 0.f;
    #pragma unroll 4
    for (int k = 0; k < 128; k++) {
        float a[8];
        #pragma unroll
        for (int i = 0; i < 8; i++) a[i] = sA[(r0 + i) * 129 + k];
        float4 b0 = *(float4*)(sW + k * 128 + c0);
        float4 b1 = *(float4*)(sW + k * 128 + c0 + 4);
        #pragma unroll
        for (int i = 0; i < 8; i++) {
            acc[i][0] = fmaf(a[i], b0.x, acc[i][0]);
            acc[i][1] = fmaf(a[i], b0.y, acc[i][1]);
            acc[i][2] = fmaf(a[i], b0.z, acc[i][2]);
            acc[i][3] = fmaf(a[i], b0.w, acc[i][3]);
            acc[i][4] = fmaf(a[i], b1.x, acc[i][4]);
            acc[i][5] = fmaf(a[i], b1.y, acc[i][5]);
            acc[i][6] = fmaf(a[i], b1.z, acc[i][6]);
            acc[i][7] = fmaf(a[i], b1.w, acc[i][7]);
        }
    }

    // coord weight: cw[e] = sum_c silu(acc+bx1)*Wx2 + bx2 (reduce across tx lanes)
    float cw[8];
    #pragma unroll
    for (int i = 0; i < 8; i++) {
        float s = 0.f;
        #pragma unroll
        for (int j = 0; j < 8; j++) {
            float u = silu_f(acc[i][j] + sbx1[c0 + j]);
            s = fmaf(u, swx2[c0 + j], s);
        }
        cw[i] = s;
    }
    #pragma unroll
    for (int msk = 1; msk < 16; msk <<= 1) {
        #pragma unroll
        for (int i = 0; i < 8; i++)
            cw[i] += __shfl_xor_sync(0xffffffffu, cw[i], msk);
    }
    if (tx == 0) {
        #pragma unroll
        for (int i = 0; i < 8; i++) {
            int e = r0 + i, d = sDst[e];
            float c = cw[i] + bx2v;
            atomicAdd(&g_num[d * 3 + 0], sRel[e * 4 + 0] * c);
            atomicAdd(&g_num[d * 3 + 1], sRel[e * 4 + 1] * c);
            atomicAdd(&g_num[d * 3 + 2], sRel[e * 4 + 2] * c);
            atomicAdd(&g_cnt[d], 1.f);
        }
    }
}

// -------- kernel 3: x update --------
__global__ void k_xupd(const float* __restrict__ x, float* __restrict__ x_out) {
    int i = blockIdx.x * blockDim.x + threadIdx.x;
    if (i < Nn) {
        float inv = 1.f / fmaxf(g_cnt[i], 1.f);
        x_out[i * 3 + 0] = x[i * 3 + 0] + g_num[i * 3 + 0] * inv;
        x_out[i * 3 + 1] = x[i * 3 + 1] + g_num[i * 3 + 1] * inv;
        x_out[i * 3 + 2] = x[i * 3 + 2] + g_num[i * 3 + 2] * inv;
    }
}

// -------- kernel 4: g = silu([h|agg] @ Wh1 + bh1) --------
__global__ __launch_bounds__(256, 2) void k_h1(const float* __restrict__ h,
                                               const float* __restrict__ Wh1,
                                               const float* __restrict__ bh1) {
    extern __shared__ float sm[];
    float* sB = sm;
    float* sA = sm + 16384;
    const int row0 = blockIdx.x * 64;
    const int tid = threadIdx.x;
    const int tx = tid & 15, ty = tid >> 4;
    const int r0 = ty * 4, c0 = tx * 8;
    float acc[4][8] = {};

    for (int half = 0; half < 2; half++) {
        const float* Ap = half ? g_agg : h;
        const float* Bp = Wh1 + (size_t)half * 16384;
        __syncthreads();
        for (int i = tid; i < 4096; i += 256)
            ((float4*)sB)[i] = ((const float4*)Bp)[i];
        for (int i = tid; i < 64 * 32; i += 256) {
            int r = i >> 5, c4 = i & 31;
            float4 v = make_float4(0.f, 0.f, 0.f, 0.f);
            if (row0 + r < Nn) v = *((const float4*)(Ap + (size_t)(row0 + r) * 128 + c4 * 4));
            float* dp = sA + r * 129 + c4 * 4;
            dp[0] = v.x; dp[1] = v.y; dp[2] = v.z; dp[3] = v.w;
        }
        __syncthreads();
        #pragma unroll 4
        for (int k = 0; k < 128; k++) {
            float a[4];
            #pragma unroll
            for (int i = 0; i < 4; i++) a[i] = sA[(r0 + i) * 129 + k];
            float4 b0 = *(float4*)(sB + k * 128 + c0);
            float4 b1 = *(float4*)(sB + k * 128 + c0 + 4);
            #pragma unroll
            for (int i = 0; i < 4; i++) {
                acc[i][0] = fmaf(a[i], b0.x, acc[i][0]);
                acc[i][1] = fmaf(a[i], b0.y, acc[i][1]);
                acc[i][2] = fmaf(a[i], b0.z, acc[i][2]);
                acc[i][3] = fmaf(a[i], b0.w, acc[i][3]);
                acc[i][4] = fmaf(a[i], b1.x, acc[i][4]);
                acc[i][5] = fmaf(a[i], b1.y, acc[i][5]);
                acc[i][6] = fmaf(a[i], b1.z, acc[i][6]);
                acc[i][7] = fmaf(a[i], b1.w, acc[i][7]);
            }
        }
    }
    #pragma unroll
    for (int i = 0; i < 4; i++) {
        int gr = row0 + r0 + i;
        if (gr < Nn) {
            #pragma unroll
            for (int j = 0; j < 8; j++)
                g_G[(size_t)gr * 128 + c0 + j] = silu_f(acc[i][j] + bh1[c0 + j]);
        }
    }
}

// -------- kernel 5: h_out = LN(h + g @ Wh2 + bh2) --------
__global__ __launch_bounds__(256, 2) void k_h2(const float* __restrict__ h,
                                               const float* __restrict__ Wh2,
                                               const float* __restrict__ bh2,
                                               const float* __restrict__ gamma,
                                               const float* __restrict__ beta,
                                               float* __restrict__ h_out) {
    extern __shared__ float sm[];
    float* sB = sm;
    float* sA = sm + 16384;
    const int row0 = blockIdx.x * 64;
    const int tid = threadIdx.x;
    const int tx = tid & 15, ty = tid >> 4;
    const int r0 = ty * 4, c0 = tx * 8;

    for (int i = tid; i < 4096; i += 256)
        ((float4*)sB)[i] = ((const float4*)Wh2)[i];
    for (int i = tid; i < 64 * 32; i += 256) {
        int r = i >> 5, c4 = i & 31;
        float4 v = make_float4(0.f, 0.f, 0.f, 0.f);
        if (row0 + r < Nn) v = *((const float4*)(g_G + (size_t)(row0 + r) * 128 + c4 * 4));
        float* dp = sA + r * 129 + c4 * 4;
        dp[0] = v.x; dp[1] = v.y; dp[2] = v.z; dp[3] = v.w;
    }
    __syncthreads();

    float acc[4][8] = {};
    #pragma unroll 4
    for (int k = 0; k < 128; k++) {
        float a[4];
        #pragma unroll
        for (int i = 0; i < 4; i++) a[i] = sA[(r0 + i) * 129 + k];
        float4 b0 = *(float4*)(sB + k * 128 + c0);
        float4 b1 = *(float4*)(sB + k * 128 + c0 + 4);
        #pragma unroll
        for (int i = 0; i < 4; i++) {
            acc[i][0] = fmaf(a[i], b0.x, acc[i][0]);
            acc[i][1] = fmaf(a[i], b0.y, acc[i][1]);
            acc[i][2] = fmaf(a[i], b0.z, acc[i][2]);
            acc[i][3] = fmaf(a[i], b0.w, acc[i][3]);
            acc[i][4] = fmaf(a[i], b1.x, acc[i][4]);
            acc[i][5] = fmaf(a[i], b1.y, acc[i][5]);
            acc[i][6] = fmaf(a[i], b1.z, acc[i][6]);
            acc[i][7] = fmaf(a[i], b1.w, acc[i][7]);
        }
    }

    #pragma unroll
    for (int i = 0; i < 4; i++) {
        int gr = row0 + r0 + i;
        float v[8];
        float4 h0 = make_float4(0.f, 0.f, 0.f, 0.f), h1 = h0;
        if (gr < Nn) {
            h0 = *(const float4*)(h + (size_t)gr * 128 + c0);
            h1 = *(const float4*)(h + (size_t)gr * 128 + c0 + 4);
        }
        v[0] = h0.x + acc[i][0] + bh2[c0 + 0];
        v[1] = h0.y + acc[i][1] + bh2[c0 + 1];
        v[2] = h0.z + acc[i][2] + bh2[c0 + 2];
        v[3] = h0.w + acc[i][3] + bh2[c0 + 3];
        v[4] = h1.x + acc[i][4] + bh2[c0 + 4];
        v[5] = h1.y + acc[i][5] + bh2[c0 + 5];
        v[6] = h1.z + acc[i][6] + bh2[c0 + 6];
        v[7] = h1.w + acc[i][7] + bh2[c0 + 7];
        float s1 = 0.f, s2 = 0.f;
        #pragma unroll
        for (int j = 0; j < 8; j++) { s1 += v[j]; s2 = fmaf(v[j], v[j], s2); }
        #pragma unroll
        for (int msk = 1; msk < 16; msk <<= 1) {
            s1 += __shfl_xor_sync(0xffffffffu, s1, msk);
            s2 += __shfl_xor_sync(0xffffffffu, s2, msk);
        }
        float mu = s1 * (1.f / 128.f);
        float var = s2 * (1.f / 128.f) - mu * mu;
        float rs = rsqrtf(var + LN_EPS);
        if (gr < Nn) {
            #pragma unroll
            for (int j = 0; j < 8; j++)
                h_out[(size_t)gr * 128 + c0 + j] =
                    (v[j] - mu) * rs * gamma[c0 + j] + beta[c0 + j];
        }
    }
}

// -------- launch --------
extern "C" void kernel_launch(void* const* d_in, const int* in_sizes, int n_in,
                              void* d_out, int out_size) {
    const float* h    = (const float*)d_in[0];
    const float* x    = (const float*)d_in[1];
    const float* vel  = (const float*)d_in[2];
    const void*  ei   = d_in[3];
    const float* We1  = (const float*)d_in[4];
    const float* be1  = (const float*)d_in[5];
    const float* We2  = (const float*)d_in[6];
    const float* be2  = (const float*)d_in[7];
    const float* Wx1  = (const float*)d_in[8];
    const float* bx1  = (const float*)d_in[9];
    const float* Wx2  = (const float*)d_in[10];
    const float* bx2  = (const float*)d_in[11];
    const float* Wh1  = (const float*)d_in[12];
    const float* bh1  = (const float*)d_in[13];
    const float* Wh2  = (const float*)d_in[14];
    const float* bh2  = (const float*)d_in[15];
    const float* gam  = (const float*)d_in[16];
    const float* bet  = (const float*)d_in[17];

    float* out_h = (float*)d_out;
    float* out_x = out_h + (size_t)Nn * 128;
    float* out_m = out_x + (size_t)Nn * 3;

    const int SM_NP = (16384 + 64 * 129) * 4;   // 98560 B
    const int SM_E  = EO_TOT * 4;               // 148480 B

    cudaFuncSetAttribute(k_nodeprep, cudaFuncAttributeMaxDynamicSharedMemorySize, SM_NP);
    cudaFuncSetAttribute(k_edge,     cudaFuncAttributeMaxDynamicSharedMemorySize, SM_E);
    cudaFuncSetAttribute(k_h1,       cudaFuncAttributeMaxDynamicSharedMemorySize, SM_NP);
    cudaFuncSetAttribute(k_h2,       cudaFuncAttributeMaxDynamicSharedMemorySize, SM_NP);

    k_zero<<<2048, 256>>>(ei);
    k_nodeprep<<<dim3((Nn + 63) / 64, 2), 256, SM_NP>>>(h, We1);
    k_edge<<<Ee / 128, 256, SM_E>>>(x, vel, ei, We1, be1, We2, be2,
                                    Wx1, bx1, Wx2, bx2, out_m);
    k_xupd<<<(Nn + 255) / 256, 256>>>(x, out_x);
    k_h1<<<(Nn + 63) / 64, 256, SM_NP>>>(h, Wh1, bh1);
    k_h2<<<(Nn + 63) / 64, 256, SM_NP>>>(h, Wh2, bh2, gam, bet, out_h);
}

// round 8
// speedup vs baseline: 1.8155x; 1.8155x over previous
#include <cuda_runtime.h>
#include <cstdint>

#define Nn 50000
#define Ee 800000
#define NTILE 6250
#define LN_EPS 1e-5f

// -------- scratch --------
__device__ __align__(16) float g_PQ[(size_t)Nn * 256];
__device__ __align__(16) float g_agg[(size_t)Nn * 128];
__device__ __align__(16) float g_G[(size_t)Nn * 128];
__device__ float g_num[Nn * 3];
__device__ float g_cnt[Nn];
__device__ int   g_is64;

__device__ __forceinline__ float silu_f(float v) {
    return __fdividef(v, 1.f + __expf(-v));
}
__device__ __forceinline__ int eidx(const void* p, long long i) {
    if (g_is64) return (int)((const long long*)p)[i];
    return ((const int*)p)[i];
}
__device__ __forceinline__ void red4(float* p, float a, float b, float c, float d) {
    asm volatile("red.global.add.v4.f32 [%0], {%1,%2,%3,%4};"
                 :: "l"(p), "f"(a), "f"(b), "f"(c), "f"(d) : "memory");
}
__device__ __forceinline__ void red2(float* p, float a, float b) {
    asm volatile("red.global.add.v2.f32 [%0], {%1,%2};"
                 :: "l"(p), "f"(a), "f"(b) : "memory");
}
__device__ __forceinline__ uint32_t f2tf32(float f) {
    uint32_t r;
    asm("cvt.rna.tf32.f32 %0, %1;" : "=r"(r) : "f"(f));
    return r;
}
__device__ __forceinline__ void mma_tf32(float* c, const uint32_t* a, const uint32_t* b) {
    asm volatile("mma.sync.aligned.m16n8k8.row.col.f32.tf32.tf32.f32 "
        "{%0,%1,%2,%3}, {%4,%5,%6,%7}, {%8,%9}, {%0,%1,%2,%3};"
        : "+f"(c[0]), "+f"(c[1]), "+f"(c[2]), "+f"(c[3])
        : "r"(a[0]), "r"(a[1]), "r"(a[2]), "r"(a[3]), "r"(b[0]), "r"(b[1]));
}

// -------- kernel 0: zero scratch + dtype detect --------
__global__ void k_zero(const void* __restrict__ ei) {
    if (blockIdx.x == 0 && threadIdx.x == 0) {
        const int* w = (const int*)ei;
        int all0 = 1;
        #pragma unroll 1
        for (int i = 0; i < 64; i++) if (w[2 * i + 1] != 0) all0 = 0;
        g_is64 = all0;
    }
    size_t i = (size_t)blockIdx.x * blockDim.x + threadIdx.x;
    size_t stride = (size_t)gridDim.x * blockDim.x;
    for (size_t j = i; j < (size_t)Nn * 128; j += stride) g_agg[j] = 0.f;
    for (size_t j = i; j < (size_t)Nn * 3;   j += stride) g_num[j] = 0.f;
    for (size_t j = i; j < (size_t)Nn;       j += stride) g_cnt[j] = 0.f;
}

// -------- kernel 1: [P|Q] = h @ We1[0:128] , h @ We1[128:256] --------
__global__ __launch_bounds__(256, 2) void k_nodeprep(const float* __restrict__ h,
                                                     const float* __restrict__ We1) {
    extern __shared__ float sm[];
    float* sB = sm;
    float* sA = sm + 16384;
    const int half = blockIdx.y;
    const float* Wb = We1 + (size_t)half * 16384;
    const int row0 = blockIdx.x * 64;
    const int tid = threadIdx.x;

    for (int i = tid; i < 4096; i += 256)
        ((float4*)sB)[i] = ((const float4*)Wb)[i];
    for (int i = tid; i < 64 * 32; i += 256) {
        int r = i >> 5, c4 = i & 31;
        float4 v = make_float4(0.f, 0.f, 0.f, 0.f);
        if (row0 + r < Nn) v = *((const float4*)(h + (size_t)(row0 + r) * 128 + c4 * 4));
        float* dp = sA + r * 129 + c4 * 4;
        dp[0] = v.x; dp[1] = v.y; dp[2] = v.z; dp[3] = v.w;
    }
    __syncthreads();

    const int tx = tid & 15, ty = tid >> 4;
    const int r0 = ty * 4, c0 = tx * 8;
    float acc[4][8] = {};
    #pragma unroll 4
    for (int k = 0; k < 128; k++) {
        float a[4];
        #pragma unroll
        for (int i = 0; i < 4; i++) a[i] = sA[(r0 + i) * 129 + k];
        float4 b0 = *(float4*)(sB + k * 128 + c0);
        float4 b1 = *(float4*)(sB + k * 128 + c0 + 4);
        #pragma unroll
        for (int i = 0; i < 4; i++) {
            acc[i][0] = fmaf(a[i], b0.x, acc[i][0]);
            acc[i][1] = fmaf(a[i], b0.y, acc[i][1]);
            acc[i][2] = fmaf(a[i], b0.z, acc[i][2]);
            acc[i][3] = fmaf(a[i], b0.w, acc[i][3]);
            acc[i][4] = fmaf(a[i], b1.x, acc[i][4]);
            acc[i][5] = fmaf(a[i], b1.y, acc[i][5]);
            acc[i][6] = fmaf(a[i], b1.z, acc[i][6]);
            acc[i][7] = fmaf(a[i], b1.w, acc[i][7]);
        }
    }
    #pragma unroll
    for (int i = 0; i < 4; i++) {
        int gr = row0 + r0 + i;
        if (gr < Nn) {
            float* o = g_PQ + (size_t)gr * 256 + half * 128 + c0;
            *(float4*)o       = make_float4(acc[i][0], acc[i][1], acc[i][2], acc[i][3]);
            *(float4*)(o + 4) = make_float4(acc[i][4], acc[i][5], acc[i][6], acc[i][7]);
        }
    }
}

// -------- kernel 2: persistent fused edge pipeline (mma.sync tf32) --------
// smem float offsets (stride 132 tiles)
#define SB1  0        // We2^T tf32 [n][k]  128*132 = 16896
#define SB2  16896    // Wx1^T tf32
#define SA   33792    // A tile tf32 [row][k] 128*132
#define SW1G 50688    // 11*128
#define SBE1 52096
#define SBE2 52224
#define SBX1 52352
#define SWX2 52480
#define SGEO 52608    // 128*12
#define SREL 54144    // 128*4
#define SSRC 54656
#define SDST 54784
#define SCW  54912    // 128*4
#define SMT  55424    // floats -> 221696 bytes

__device__ __forceinline__ void warp_gemm_tf32(const uint32_t* __restrict__ sA,
                                               const uint32_t* __restrict__ sB,
                                               float C[16][4],
                                               int m0, int n0, int gid, int tig) {
    #pragma unroll 4
    for (int ks = 0; ks < 16; ks++) {
        const int k0 = ks * 8;
        uint32_t a[4][4];
        #pragma unroll
        for (int mt = 0; mt < 4; mt++) {
            const int r = m0 + mt * 16 + gid;
            a[mt][0] = sA[r * 132 + k0 + tig];
            a[mt][1] = sA[(r + 8) * 132 + k0 + tig];
            a[mt][2] = sA[r * 132 + k0 + tig + 4];
            a[mt][3] = sA[(r + 8) * 132 + k0 + tig + 4];
        }
        uint32_t b[4][2];
        #pragma unroll
        for (int nt = 0; nt < 4; nt++) {
            const int n = n0 + nt * 8 + gid;
            b[nt][0] = sB[n * 132 + k0 + tig];
            b[nt][1] = sB[n * 132 + k0 + tig + 4];
        }
        #pragma unroll
        for (int mt = 0; mt < 4; mt++)
            #pragma unroll
            for (int nt = 0; nt < 4; nt++)
                mma_tf32(C[mt * 4 + nt], a[mt], b[nt]);
    }
}

__global__ __launch_bounds__(256, 1) void k_edge(
    const float* __restrict__ x, const float* __restrict__ vel,
    const void* __restrict__ ei,
    const float* __restrict__ We1, const float* __restrict__ be1,
    const float* __restrict__ We2, const float* __restrict__ be2,
    const float* __restrict__ Wx1, const float* __restrict__ bx1,
    const float* __restrict__ Wx2, const float* __restrict__ bx2,
    float* __restrict__ m_out)
{
    extern __shared__ __align__(16) float sm[];
    uint32_t* smu = (uint32_t*)sm;
    const int tid = threadIdx.x, wid = tid >> 5, lane = tid & 31;
    const int gid = lane >> 2, tig = lane & 3;
    int* sSrc = (int*)&sm[SSRC];
    int* sDst = (int*)&sm[SDST];

    // one-time: transpose weights to [n][k] tf32, small params
    for (int i = tid; i < 16384; i += 256) {
        int k = i >> 7, n = i & 127;
        smu[SB1 + n * 132 + k] = f2tf32(We2[i]);
        smu[SB2 + n * 132 + k] = f2tf32(Wx1[i]);
    }
    for (int i = tid; i < 1408; i += 256) sm[SW1G + i] = We1[32768 + i];
    if (tid < 128) { sm[SBE1 + tid] = be1[tid]; sm[SBE2 + tid] = be2[tid];
                     sm[SBX1 + tid] = bx1[tid]; sm[SWX2 + tid] = Wx2[tid]; }
    const float bx2v = bx2[0];

    const int tx = tid & 15, ty = tid >> 4;
    const int r0 = ty * 8, c0 = tx * 8;
    const int m0 = (wid & 1) * 64, n0 = (wid >> 1) * 32, cb = wid >> 1;

    for (long long tile = blockIdx.x; tile < NTILE; tile += gridDim.x) {
        const long long e0 = tile * 128;
        __syncthreads();

        // geometry (one edge per thread)
        if (tid < 128) {
            int e = tid;
            int s = eidx(ei, e0 + e), d = eidx(ei, (long long)Ee + e0 + e);
            sSrc[e] = s; sDst[e] = d;
            float rx = x[s * 3 + 0] - x[d * 3 + 0];
            float ry = x[s * 3 + 1] - x[d * 3 + 1];
            float rz = x[s * 3 + 2] - x[d * 3 + 2];
            float d2 = rx * rx + ry * ry + rz * rz;
            float inv = __fdividef(1.f, fmaxf(sqrtf(d2), 1e-8f));
            float hx = rx * inv, hy = ry * inv, hz = rz * inv;
            sm[SREL + e * 4 + 0] = rx; sm[SREL + e * 4 + 1] = ry; sm[SREL + e * 4 + 2] = rz;
            sm[SGEO + e * 12 + 0] = d2;
            #pragma unroll
            for (int i = 0; i < 5; i++) {
                const float* vs = vel + ((size_t)s * 5 + i) * 3;
                sm[SGEO + e * 12 + 1 + i] = vs[0] * hx + vs[1] * hy + vs[2] * hz;
            }
            #pragma unroll
            for (int i = 0; i < 5; i++) {
                const float* vd = vel + ((size_t)d * 5 + i) * 3;
                sm[SGEO + e * 12 + 6 + i] = vd[0] * hx + vd[1] * hy + vd[2] * hz;
            }
        }
        __syncthreads();

        // t = silu(P[src]+Q[dst]+geom@W1g+be1) -> sA (tf32)
        #pragma unroll
        for (int rr = 0; rr < 8; rr++) {
            int e = r0 + rr;
            int s = sSrc[e], d = sDst[e];
            const float* prow = g_PQ + (size_t)s * 256 + c0;
            const float* qrow = g_PQ + (size_t)d * 256 + 128 + c0;
            float4 p0 = *(const float4*)prow,  p1 = *(const float4*)(prow + 4);
            float4 q0 = *(const float4*)qrow,  q1 = *(const float4*)(qrow + 4);
            float t[8];
            t[0] = p0.x + q0.x; t[1] = p0.y + q0.y; t[2] = p0.z + q0.z; t[3] = p0.w + q0.w;
            t[4] = p1.x + q1.x; t[5] = p1.y + q1.y; t[6] = p1.z + q1.z; t[7] = p1.w + q1.w;
            #pragma unroll
            for (int j = 0; j < 8; j++) t[j] += sm[SBE1 + c0 + j];
            #pragma unroll
            for (int g = 0; g < 11; g++) {
                float gv = sm[SGEO + e * 12 + g];
                #pragma unroll
                for (int j = 0; j < 8; j++) t[j] = fmaf(gv, sm[SW1G + g * 128 + c0 + j], t[j]);
            }
            uint32_t* dp = smu + SA + e * 132 + c0;
            #pragma unroll
            for (int j = 0; j < 8; j++) dp[j] = f2tf32(silu_f(t[j]));
        }
        __syncthreads();

        // GEMM1: C = t @ We2
        float C[16][4];
        #pragma unroll
        for (int i = 0; i < 16; i++)
            { C[i][0] = 0.f; C[i][1] = 0.f; C[i][2] = 0.f; C[i][3] = 0.f; }
        warp_gemm_tf32(smu + SA, smu + SB1, C, m0, n0, gid, tig);
        __syncthreads();

        // epilogue1: m = silu(C+be2); fp32 -> m_out + agg; tf32 -> sA for GEMM2
        #pragma unroll
        for (int mt = 0; mt < 4; mt++) {
            const int ra = m0 + mt * 16 + gid, rb = ra + 8;
            const int da = sDst[ra], db = sDst[rb];
            #pragma unroll
            for (int nt = 0; nt < 4; nt++) {
                const int col = n0 + nt * 8 + tig * 2;
                float* c = C[mt * 4 + nt];
                float m00 = silu_f(c[0] + sm[SBE2 + col]);
                float m01 = silu_f(c[1] + sm[SBE2 + col + 1]);
                float m10 = silu_f(c[2] + sm[SBE2 + col]);
                float m11 = silu_f(c[3] + sm[SBE2 + col + 1]);
                smu[SA + ra * 132 + col]     = f2tf32(m00);
                smu[SA + ra * 132 + col + 1] = f2tf32(m01);
                smu[SA + rb * 132 + col]     = f2tf32(m10);
                smu[SA + rb * 132 + col + 1] = f2tf32(m11);
                *(float2*)(m_out + (size_t)(e0 + ra) * 128 + col) = make_float2(m00, m01);
                *(float2*)(m_out + (size_t)(e0 + rb) * 128 + col) = make_float2(m10, m11);
                red2(g_agg + (size_t)da * 128 + col, m00, m01);
                red2(g_agg + (size_t)db * 128 + col, m10, m11);
            }
        }
        __syncthreads();

        // GEMM2: C = m @ Wx1
        #pragma unroll
        for (int i = 0; i < 16; i++)
            { C[i][0] = 0.f; C[i][1] = 0.f; C[i][2] = 0.f; C[i][3] = 0.f; }
        warp_gemm_tf32(smu + SA, smu + SB2, C, m0, n0, gid, tig);

        // cw partials: sum over warp's 32 cols of silu(C+bx1)*Wx2
        float accA[4] = {0.f, 0.f, 0.f, 0.f}, accB[4] = {0.f, 0.f, 0.f, 0.f};
        #pragma unroll
        for (int mt = 0; mt < 4; mt++) {
            #pragma unroll
            for (int nt = 0; nt < 4; nt++) {
                const int col = n0 + nt * 8 + tig * 2;
                float* c = C[mt * 4 + nt];
                float w0 = sm[SWX2 + col], w1 = sm[SWX2 + col + 1];
                float b0 = sm[SBX1 + col], b1 = sm[SBX1 + col + 1];
                accA[mt] = fmaf(silu_f(c[0] + b0), w0, accA[mt]);
                accA[mt] = fmaf(silu_f(c[1] + b1), w1, accA[mt]);
                accB[mt] = fmaf(silu_f(c[2] + b0), w0, accB[mt]);
                accB[mt] = fmaf(silu_f(c[3] + b1), w1, accB[mt]);
            }
        }
        #pragma unroll
        for (int mt = 0; mt < 4; mt++) {
            accA[mt] += __shfl_xor_sync(0xffffffffu, accA[mt], 1);
            accA[mt] += __shfl_xor_sync(0xffffffffu, accA[mt], 2);
            accB[mt] += __shfl_xor_sync(0xffffffffu, accB[mt], 1);
            accB[mt] += __shfl_xor_sync(0xffffffffu, accB[mt], 2);
        }
        if (tig == 0) {
            #pragma unroll
            for (int mt = 0; mt < 4; mt++) {
                sm[SCW + (m0 + mt * 16 + gid) * 4 + cb]     = accA[mt];
                sm[SCW + (m0 + mt * 16 + gid + 8) * 4 + cb] = accB[mt];
            }
        }
        __syncthreads();

        if (tid < 128) {
            float c = sm[SCW + tid * 4] + sm[SCW + tid * 4 + 1]
                    + sm[SCW + tid * 4 + 2] + sm[SCW + tid * 4 + 3] + bx2v;
            int d = sDst[tid];
            atomicAdd(&g_num[d * 3 + 0], sm[SREL + tid * 4 + 0] * c);
            atomicAdd(&g_num[d * 3 + 1], sm[SREL + tid * 4 + 1] * c);
            atomicAdd(&g_num[d * 3 + 2], sm[SREL + tid * 4 + 2] * c);
            atomicAdd(&g_cnt[d], 1.f);
        }
    }
}

// -------- kernel 3: x update --------
__global__ void k_xupd(const float* __restrict__ x, float* __restrict__ x_out) {
    int i = blockIdx.x * blockDim.x + threadIdx.x;
    if (i < Nn) {
        float inv = __fdividef(1.f, fmaxf(g_cnt[i], 1.f));
        x_out[i * 3 + 0] = x[i * 3 + 0] + g_num[i * 3 + 0] * inv;
        x_out[i * 3 + 1] = x[i * 3 + 1] + g_num[i * 3 + 1] * inv;
        x_out[i * 3 + 2] = x[i * 3 + 2] + g_num[i * 3 + 2] * inv;
    }
}

// -------- kernel 4: g = silu([h|agg] @ Wh1 + bh1) --------
__global__ __launch_bounds__(256, 2) void k_h1(const float* __restrict__ h,
                                               const float* __restrict__ Wh1,
                                               const float* __restrict__ bh1) {
    extern __shared__ float sm[];
    float* sB = sm;
    float* sA = sm + 16384;
    const int row0 = blockIdx.x * 64;
    const int tid = threadIdx.x;
    const int tx = tid & 15, ty = tid >> 4;
    const int r0 = ty * 4, c0 = tx * 8;
    float acc[4][8] = {};

    for (int half = 0; half < 2; half++) {
        const float* Ap = half ? g_agg : h;
        const float* Bp = Wh1 + (size_t)half * 16384;
        __syncthreads();
        for (int i = tid; i < 4096; i += 256)
            ((float4*)sB)[i] = ((const float4*)Bp)[i];
        for (int i = tid; i < 64 * 32; i += 256) {
            int r = i >> 5, c4 = i & 31;
            float4 v = make_float4(0.f, 0.f, 0.f, 0.f);
            if (row0 + r < Nn) v = *((const float4*)(Ap + (size_t)(row0 + r) * 128 + c4 * 4));
            float* dp = sA + r * 129 + c4 * 4;
            dp[0] = v.x; dp[1] = v.y; dp[2] = v.z; dp[3] = v.w;
        }
        __syncthreads();
        #pragma unroll 4
        for (int k = 0; k < 128; k++) {
            float a[4];
            #pragma unroll
            for (int i = 0; i < 4; i++) a[i] = sA[(r0 + i) * 129 + k];
            float4 b0 = *(float4*)(sB + k * 128 + c0);
            float4 b1 = *(float4*)(sB + k * 128 + c0 + 4);
            #pragma unroll
            for (int i = 0; i < 4; i++) {
                acc[i][0] = fmaf(a[i], b0.x, acc[i][0]);
                acc[i][1] = fmaf(a[i], b0.y, acc[i][1]);
                acc[i][2] = fmaf(a[i], b0.z, acc[i][2]);
                acc[i][3] = fmaf(a[i], b0.w, acc[i][3]);
                acc[i][4] = fmaf(a[i], b1.x, acc[i][4]);
                acc[i][5] = fmaf(a[i], b1.y, acc[i][5]);
                acc[i][6] = fmaf(a[i], b1.z, acc[i][6]);
                acc[i][7] = fmaf(a[i], b1.w, acc[i][7]);
            }
        }
    }
    #pragma unroll
    for (int i = 0; i < 4; i++) {
        int gr = row0 + r0 + i;
        if (gr < Nn) {
            #pragma unroll
            for (int j = 0; j < 8; j++)
                g_G[(size_t)gr * 128 + c0 + j] = silu_f(acc[i][j] + bh1[c0 + j]);
        }
    }
}

// -------- kernel 5: h_out = LN(h + g @ Wh2 + bh2) --------
__global__ __launch_bounds__(256, 2) void k_h2(const float* __restrict__ h,
                                               const float* __restrict__ Wh2,
                                               const float* __restrict__ bh2,
                                               const float* __restrict__ gamma,
                                               const float* __restrict__ beta,
                                               float* __restrict__ h_out) {
    extern __shared__ float sm[];
    float* sB = sm;
    float* sA = sm + 16384;
    const int row0 = blockIdx.x * 64;
    const int tid = threadIdx.x;
    const int tx = tid & 15, ty = tid >> 4;
    const int r0 = ty * 4, c0 = tx * 8;

    for (int i = tid; i < 4096; i += 256)
        ((float4*)sB)[i] = ((const float4*)Wh2)[i];
    for (int i = tid; i < 64 * 32; i += 256) {
        int r = i >> 5, c4 = i & 31;
        float4 v = make_float4(0.f, 0.f, 0.f, 0.f);
        if (row0 + r < Nn) v = *((const float4*)(g_G + (size_t)(row0 + r) * 128 + c4 * 4));
        float* dp = sA + r * 129 + c4 * 4;
        dp[0] = v.x; dp[1] = v.y; dp[2] = v.z; dp[3] = v.w;
    }
    __syncthreads();

    float acc[4][8] = {};
    #pragma unroll 4
    for (int k = 0; k < 128; k++) {
        float a[4];
        #pragma unroll
        for (int i = 0; i < 4; i++) a[i] = sA[(r0 + i) * 129 + k];
        float4 b0 = *(float4*)(sB + k * 128 + c0);
        float4 b1 = *(float4*)(sB + k * 128 + c0 + 4);
        #pragma unroll
        for (int i = 0; i < 4; i++) {
            acc[i][0] = fmaf(a[i], b0.x, acc[i][0]);
            acc[i][1] = fmaf(a[i], b0.y, acc[i][1]);
            acc[i][2] = fmaf(a[i], b0.z, acc[i][2]);
            acc[i][3] = fmaf(a[i], b0.w, acc[i][3]);
            acc[i][4] = fmaf(a[i], b1.x, acc[i][4]);
            acc[i][5] = fmaf(a[i], b1.y, acc[i][5]);
            acc[i][6] = fmaf(a[i], b1.z, acc[i][6]);
            acc[i][7] = fmaf(a[i], b1.w, acc[i][7]);
        }
    }

    #pragma unroll
    for (int i = 0; i < 4; i++) {
        int gr = row0 + r0 + i;
        float v[8];
        float4 h0 = make_float4(0.f, 0.f, 0.f, 0.f), h1 = h0;
        if (gr < Nn) {
            h0 = *(const float4*)(h + (size_t)gr * 128 + c0);
            h1 = *(const float4*)(h + (size_t)gr * 128 + c0 + 4);
        }
        v[0] = h0.x + acc[i][0] + bh2[c0 + 0];
        v[1] = h0.y + acc[i][1] + bh2[c0 + 1];
        v[2] = h0.z + acc[i][2] + bh2[c0 + 2];
        v[3] = h0.w + acc[i][3] + bh2[c0 + 3];
        v[4] = h1.x + acc[i][4] + bh2[c0 + 4];
        v[5] = h1.y + acc[i][5] + bh2[c0 + 5];
        v[6] = h1.z + acc[i][6] + bh2[c0 + 6];
        v[7] = h1.w + acc[i][7] + bh2[c0 + 7];
        float s1 = 0.f, s2 = 0.f;
        #pragma unroll
        for (int j = 0; j < 8; j++) { s1 += v[j]; s2 = fmaf(v[j], v[j], s2); }
        #pragma unroll
        for (int msk = 1; msk < 16; msk <<= 1) {
            s1 += __shfl_xor_sync(0xffffffffu, s1, msk);
            s2 += __shfl_xor_sync(0xffffffffu, s2, msk);
        }
        float mu = s1 * (1.f / 128.f);
        float var = s2 * (1.f / 128.f) - mu * mu;
        float rs = rsqrtf(var + LN_EPS);
        if (gr < Nn) {
            #pragma unroll
            for (int j = 0; j < 8; j++)
                h_out[(size_t)gr * 128 + c0 + j] =
                    (v[j] - mu) * rs * gamma[c0 + j] + beta[c0 + j];
        }
    }
}

// -------- launch --------
extern "C" void kernel_launch(void* const* d_in, const int* in_sizes, int n_in,
                              void* d_out, int out_size) {
    const float* h    = (const float*)d_in[0];
    const float* x    = (const float*)d_in[1];
    const float* vel  = (const float*)d_in[2];
    const void*  ei   = d_in[3];
    const float* We1  = (const float*)d_in[4];
    const float* be1  = (const float*)d_in[5];
    const float* We2  = (const float*)d_in[6];
    const float* be2  = (const float*)d_in[7];
    const float* Wx1  = (const float*)d_in[8];
    const float* bx1  = (const float*)d_in[9];
    const float* Wx2  = (const float*)d_in[10];
    const float* bx2  = (const float*)d_in[11];
    const float* Wh1  = (const float*)d_in[12];
    const float* bh1  = (const float*)d_in[13];
    const float* Wh2  = (const float*)d_in[14];
    const float* bh2  = (const float*)d_in[15];
    const float* gam  = (const float*)d_in[16];
    const float* bet  = (const float*)d_in[17];

    float* out_h = (float*)d_out;
    float* out_x = out_h + (size_t)Nn * 128;
    float* out_m = out_x + (size_t)Nn * 3;

    const int SM_NP = (16384 + 64 * 129) * 4;   // 98560 B
    const int SM_E  = SMT * 4;                  // 221696 B

    int nsm = 148;
    cudaDeviceGetAttribute(&nsm, cudaDevAttrMultiProcessorCount, 0);

    cudaFuncSetAttribute(k_nodeprep, cudaFuncAttributeMaxDynamicSharedMemorySize, SM_NP);
    cudaFuncSetAttribute(k_edge,     cudaFuncAttributeMaxDynamicSharedMemorySize, SM_E);
    cudaFuncSetAttribute(k_h1,       cudaFuncAttributeMaxDynamicSharedMemorySize, SM_NP);
    cudaFuncSetAttribute(k_h2,       cudaFuncAttributeMaxDynamicSharedMemorySize, SM_NP);

    k_zero<<<2048, 256>>>(ei);
    k_nodeprep<<<dim3((Nn + 63) / 64, 2), 256, SM_NP>>>(h, We1);
    k_edge<<<nsm, 256, SM_E>>>(x, vel, ei, We1, be1, We2, be2,
                               Wx1, bx1, Wx2, bx2, out_m);
    k_xupd<<<(Nn + 255) / 256, 256>>>(x, out_x);
    k_h1<<<(Nn + 63) / 64, 256, SM_NP>>>(h, Wh1, bh1);
    k_h2<<<(Nn + 63) / 64, 256, SM_NP>>>(h, Wh2, bh2, gam, bet, out_h);
}

// round 9
// speedup vs baseline: 2.3614x; 1.3007x over previous
#include <cuda_runtime.h>
#include <cstdint>

#define Nn 50000
#define Ee 800000
#define NTILE 6250
#define NT128 391
#define LN_EPS 1e-5f

// -------- scratch --------
__device__ __align__(16) float g_PQ[(size_t)Nn * 256];
__device__ __align__(16) float g_agg[(size_t)Nn * 128];
__device__ __align__(16) float g_G[(size_t)Nn * 128];
__device__ float g_num[Nn * 3];
__device__ float g_cnt[Nn];
__device__ int   g_is64;

// silu via tanh: v*sigmoid(v) = 0.5v + 0.5v*tanh(0.5v)  (1 MUFU)
__device__ __forceinline__ float silu_f(float v) {
    float t;
    asm("tanh.approx.f32 %0, %1;" : "=f"(t) : "f"(0.5f * v));
    return fmaf(0.5f * v, t, 0.5f * v);
}
__device__ __forceinline__ int eidx(const void* p, long long i) {
    if (g_is64) return (int)((const long long*)p)[i];
    return ((const int*)p)[i];
}
__device__ __forceinline__ void red4(float* p, float a, float b, float c, float d) {
    asm volatile("red.global.add.v4.f32 [%0], {%1,%2,%3,%4};"
                 :: "l"(p), "f"(a), "f"(b), "f"(c), "f"(d) : "memory");
}
__device__ __forceinline__ uint32_t f2tf32(float f) {
    uint32_t r;
    asm("cvt.rna.tf32.f32 %0, %1;" : "=r"(r) : "f"(f));
    return r;
}
__device__ __forceinline__ void mma_tf32(float* c, const uint32_t* a, const uint32_t* b) {
    asm volatile("mma.sync.aligned.m16n8k8.row.col.f32.tf32.tf32.f32 "
        "{%0,%1,%2,%3}, {%4,%5,%6,%7}, {%8,%9}, {%0,%1,%2,%3};"
        : "+f"(c[0]), "+f"(c[1]), "+f"(c[2]), "+f"(c[3])
        : "r"(a[0]), "r"(a[1]), "r"(a[2]), "r"(a[3]), "r"(b[0]), "r"(b[1]));
}

// warp computes a 32x32 block: C[8][4] = (mt 0..1)x(nt 0..3) m16n8k8 tiles
__device__ __forceinline__ void warp_gemm32(const uint32_t* __restrict__ sA,
                                            const uint32_t* __restrict__ sB,
                                            float C[8][4],
                                            int m0, int n0, int gid, int tig) {
    #pragma unroll 4
    for (int ks = 0; ks < 16; ks++) {
        const int k0 = ks * 8;
        uint32_t a[2][4];
        #pragma unroll
        for (int mt = 0; mt < 2; mt++) {
            const int r = m0 + mt * 16 + gid;
            a[mt][0] = sA[r * 132 + k0 + tig];
            a[mt][1] = sA[(r + 8) * 132 + k0 + tig];
            a[mt][2] = sA[r * 132 + k0 + tig + 4];
            a[mt][3] = sA[(r + 8) * 132 + k0 + tig + 4];
        }
        uint32_t b[4][2];
        #pragma unroll
        for (int nt = 0; nt < 4; nt++) {
            const int n = n0 + nt * 8 + gid;
            b[nt][0] = sB[n * 132 + k0 + tig];
            b[nt][1] = sB[n * 132 + k0 + tig + 4];
        }
        #pragma unroll
        for (int mt = 0; mt < 2; mt++)
            #pragma unroll
            for (int nt = 0; nt < 4; nt++)
                mma_tf32(C[mt * 4 + nt], a[mt], b[nt]);
    }
}

// -------- kernel 0: zero scratch + dtype detect --------
__global__ void k_zero(const void* __restrict__ ei) {
    if (blockIdx.x == 0 && threadIdx.x == 0) {
        const int* w = (const int*)ei;
        int all0 = 1;
        #pragma unroll 1
        for (int i = 0; i < 64; i++) if (w[2 * i + 1] != 0) all0 = 0;
        g_is64 = all0;
    }
    size_t i = (size_t)blockIdx.x * blockDim.x + threadIdx.x;
    size_t stride = (size_t)gridDim.x * blockDim.x;
    for (size_t j = i; j < (size_t)Nn * 128; j += stride) g_agg[j] = 0.f;
    for (size_t j = i; j < (size_t)Nn * 3;   j += stride) g_num[j] = 0.f;
    for (size_t j = i; j < (size_t)Nn;       j += stride) g_cnt[j] = 0.f;
}

// ===== node-side tf32 GEMM kernels (128-row tiles, 512 threads, 16 warps) =====
#define NB1 0
#define NB2 16896
#define NA  33792
#define NSM ((NB2 + 16896 * 2) * 4)    // 202752 B (3 buffers)
#define NSM2 ((16896 * 2) * 4)         // 135168 B (2 buffers)

// load a 128x128 fp32 row-major gmem tile into tf32 smem [r][k] stride 132
__device__ __forceinline__ void load_a_tile(uint32_t* __restrict__ dst,
                                            const float* __restrict__ src,
                                            int row0, int tid) {
    for (int i = tid; i < 128 * 32; i += 512) {
        int r = i >> 5, c4 = (i & 31) * 4;
        float4 v = make_float4(0.f, 0.f, 0.f, 0.f);
        if (row0 + r < Nn) v = *(const float4*)(src + (size_t)(row0 + r) * 128 + c4);
        uint32_t* dp = dst + r * 132 + c4;
        dp[0] = f2tf32(v.x); dp[1] = f2tf32(v.y); dp[2] = f2tf32(v.z); dp[3] = f2tf32(v.w);
    }
}

// -------- kernel 1: [P|Q] = h @ We1[0:128], h @ We1[128:256] --------
__global__ __launch_bounds__(512, 1) void k_nodeprep(const float* __restrict__ h,
                                                     const float* __restrict__ We1) {
    extern __shared__ __align__(16) float sm[];
    uint32_t* smu = (uint32_t*)sm;
    const int tid = threadIdx.x, wid = tid >> 5, lane = tid & 31;
    const int gid = lane >> 2, tig = lane & 3;
    const int row0 = blockIdx.x * 128;

    for (int i = tid; i < 16384; i += 512) {
        int k = i >> 7, n = i & 127;
        smu[NB1 + n * 132 + k] = f2tf32(We1[i]);
        smu[NB2 + n * 132 + k] = f2tf32(We1[16384 + i]);
    }
    load_a_tile(smu + NA, h, row0, tid);
    __syncthreads();

    const int m0 = (wid & 3) * 32, n0 = (wid >> 2) * 32;
    float C1[8][4] = {}, C2[8][4] = {};
    warp_gemm32(smu + NA, smu + NB1, C1, m0, n0, gid, tig);
    warp_gemm32(smu + NA, smu + NB2, C2, m0, n0, gid, tig);

    #pragma unroll
    for (int mt = 0; mt < 2; mt++) {
        const int ra = m0 + mt * 16 + gid, rb = ra + 8;
        #pragma unroll
        for (int nt = 0; nt < 4; nt++) {
            const int col = n0 + nt * 8 + tig * 2;
            float* c1 = C1[mt * 4 + nt];
            float* c2 = C2[mt * 4 + nt];
            if (row0 + ra < Nn) {
                float* o = g_PQ + (size_t)(row0 + ra) * 256;
                *(float2*)(o + col)       = make_float2(c1[0], c1[1]);
                *(float2*)(o + 128 + col) = make_float2(c2[0], c2[1]);
            }
            if (row0 + rb < Nn) {
                float* o = g_PQ + (size_t)(row0 + rb) * 256;
                *(float2*)(o + col)       = make_float2(c1[2], c1[3]);
                *(float2*)(o + 128 + col) = make_float2(c2[2], c2[3]);
            }
        }
    }
}

// -------- kernel 2: persistent fused edge pipeline (tf32 mma, 512 thr) --------
// smem float offsets (stride-132 tiles)
#define SB1  0
#define SB2  16896
#define SA   33792
#define SW1G 50688
#define SBE1 52096
#define SBE2 52224
#define SBX1 52352
#define SWX2 52480
#define SGEO 52608
#define SREL 54144
#define SSRC 54656
#define SDST 54784
#define SCW  54912
#define SMT  55424   // floats -> 221696 B

__global__ __launch_bounds__(512, 1) void k_edge(
    const float* __restrict__ x, const float* __restrict__ vel,
    const void* __restrict__ ei,
    const float* __restrict__ We1, const float* __restrict__ be1,
    const float* __restrict__ We2, const float* __restrict__ be2,
    const float* __restrict__ Wx1, const float* __restrict__ bx1,
    const float* __restrict__ Wx2, const float* __restrict__ bx2,
    float* __restrict__ m_out)
{
    extern __shared__ __align__(16) float sm[];
    uint32_t* smu = (uint32_t*)sm;
    const int tid = threadIdx.x, wid = tid >> 5, lane = tid & 31;
    const int gid = lane >> 2, tig = lane & 3;
    int* sSrc = (int*)&sm[SSRC];
    int* sDst = (int*)&sm[SDST];

    for (int i = tid; i < 16384; i += 512) {
        int k = i >> 7, n = i & 127;
        smu[SB1 + n * 132 + k] = f2tf32(We2[i]);
        smu[SB2 + n * 132 + k] = f2tf32(Wx1[i]);
    }
    for (int i = tid; i < 1408; i += 512) sm[SW1G + i] = We1[32768 + i];
    if (tid < 128) { sm[SBE1 + tid] = be1[tid]; sm[SBE2 + tid] = be2[tid];
                     sm[SBX1 + tid] = bx1[tid]; sm[SWX2 + tid] = Wx2[tid]; }
    const float bx2v = bx2[0];

    const int tx = tid & 15, ty = tid >> 4;
    const int r0 = ty * 4, c0 = tx * 8;
    const int m0 = (wid & 3) * 32, n0 = (wid >> 2) * 32;
    const int drow = wid * 8 + (lane >> 2);      // dump row
    const int dc4 = (lane & 3) * 4;              // dump col base

    for (long long tile = blockIdx.x; tile < NTILE; tile += gridDim.x) {
        const long long e0 = tile * 128;
        __syncthreads();

        if (tid < 128) {
            int e = tid;
            int s = eidx(ei, e0 + e), d = eidx(ei, (long long)Ee + e0 + e);
            sSrc[e] = s; sDst[e] = d;
            float rx = x[s * 3 + 0] - x[d * 3 + 0];
            float ry = x[s * 3 + 1] - x[d * 3 + 1];
            float rz = x[s * 3 + 2] - x[d * 3 + 2];
            float d2 = rx * rx + ry * ry + rz * rz;
            float inv = __frcp_rn(fmaxf(sqrtf(d2), 1e-8f));
            float hx = rx * inv, hy = ry * inv, hz = rz * inv;
            sm[SREL + e * 4 + 0] = rx; sm[SREL + e * 4 + 1] = ry; sm[SREL + e * 4 + 2] = rz;
            sm[SGEO + e * 12 + 0] = d2;
            #pragma unroll
            for (int i = 0; i < 5; i++) {
                const float* vs = vel + ((size_t)s * 5 + i) * 3;
                sm[SGEO + e * 12 + 1 + i] = vs[0] * hx + vs[1] * hy + vs[2] * hz;
            }
            #pragma unroll
            for (int i = 0; i < 5; i++) {
                const float* vd = vel + ((size_t)d * 5 + i) * 3;
                sm[SGEO + e * 12 + 6 + i] = vd[0] * hx + vd[1] * hy + vd[2] * hz;
            }
        }
        __syncthreads();

        // t = silu(P[src]+Q[dst]+geom@W1g+be1) -> sA (tf32), 4 rows/thread
        #pragma unroll
        for (int rr = 0; rr < 4; rr++) {
            int e = r0 + rr;
            int s = sSrc[e], d = sDst[e];
            const float* prow = g_PQ + (size_t)s * 256 + c0;
            const float* qrow = g_PQ + (size_t)d * 256 + 128 + c0;
            float4 p0 = *(const float4*)prow,  p1 = *(const float4*)(prow + 4);
            float4 q0 = *(const float4*)qrow,  q1 = *(const float4*)(qrow + 4);
            float t[8];
            t[0] = p0.x + q0.x; t[1] = p0.y + q0.y; t[2] = p0.z + q0.z; t[3] = p0.w + q0.w;
            t[4] = p1.x + q1.x; t[5] = p1.y + q1.y; t[6] = p1.z + q1.z; t[7] = p1.w + q1.w;
            #pragma unroll
            for (int j = 0; j < 8; j++) t[j] += sm[SBE1 + c0 + j];
            #pragma unroll
            for (int g = 0; g < 11; g++) {
                float gv = sm[SGEO + e * 12 + g];
                #pragma unroll
                for (int j = 0; j < 8; j++) t[j] = fmaf(gv, sm[SW1G + g * 128 + c0 + j], t[j]);
            }
            uint32_t* dp = smu + SA + e * 132 + c0;
            #pragma unroll
            for (int j = 0; j < 8; j++) dp[j] = f2tf32(silu_f(t[j]));
        }
        __syncthreads();

        // GEMM1: C = t @ We2
        float C[8][4] = {};
        warp_gemm32(smu + SA, smu + SB1, C, m0, n0, gid, tig);
        __syncthreads();

        // epilogue1: m = silu(C+be2) -> sA as raw fp32 (HMMA truncates to tf32)
        #pragma unroll
        for (int mt = 0; mt < 2; mt++) {
            const int ra = m0 + mt * 16 + gid, rb = ra + 8;
            #pragma unroll
            for (int nt = 0; nt < 4; nt++) {
                const int col = n0 + nt * 8 + tig * 2;
                float* c = C[mt * 4 + nt];
                float b0 = sm[SBE2 + col], b1 = sm[SBE2 + col + 1];
                sm[SA + ra * 132 + col]     = silu_f(c[0] + b0);
                sm[SA + ra * 132 + col + 1] = silu_f(c[1] + b1);
                sm[SA + rb * 132 + col]     = silu_f(c[2] + b0);
                sm[SA + rb * 132 + col + 1] = silu_f(c[3] + b1);
            }
        }
        __syncthreads();

        // GEMM2: C = m @ Wx1
        #pragma unroll
        for (int i = 0; i < 8; i++)
            { C[i][0] = 0.f; C[i][1] = 0.f; C[i][2] = 0.f; C[i][3] = 0.f; }
        warp_gemm32(smu + SA, smu + SB2, C, m0, n0, gid, tig);

        // dump m (fp32) -> m_out + red4 agg (coalesced 64B segments)
        {
            const int da = sDst[drow];
            float* go = m_out + (size_t)(e0 + drow) * 128;
            float* ga = g_agg + (size_t)da * 128;
            #pragma unroll
            for (int j = 0; j < 8; j++) {
                const int col = dc4 + j * 16;
                float4 v = *(float4*)&sm[SA + drow * 132 + col];
                *(float4*)(go + col) = v;
                red4(ga + col, v.x, v.y, v.z, v.w);
            }
        }

        // epilogue2: cw partials = sum over 32 cols of silu(C+bx1)*Wx2
        float accA[2] = {0.f, 0.f}, accB[2] = {0.f, 0.f};
        #pragma unroll
        for (int mt = 0; mt < 2; mt++) {
            #pragma unroll
            for (int nt = 0; nt < 4; nt++) {
                const int col = n0 + nt * 8 + tig * 2;
                float* c = C[mt * 4 + nt];
                float w0 = sm[SWX2 + col], w1 = sm[SWX2 + col + 1];
                float b0 = sm[SBX1 + col], b1 = sm[SBX1 + col + 1];
                accA[mt] = fmaf(silu_f(c[0] + b0), w0, accA[mt]);
                accA[mt] = fmaf(silu_f(c[1] + b1), w1, accA[mt]);
                accB[mt] = fmaf(silu_f(c[2] + b0), w0, accB[mt]);
                accB[mt] = fmaf(silu_f(c[3] + b1), w1, accB[mt]);
            }
        }
        #pragma unroll
        for (int mt = 0; mt < 2; mt++) {
            accA[mt] += __shfl_xor_sync(0xffffffffu, accA[mt], 1);
            accA[mt] += __shfl_xor_sync(0xffffffffu, accA[mt], 2);
            accB[mt] += __shfl_xor_sync(0xffffffffu, accB[mt], 1);
            accB[mt] += __shfl_xor_sync(0xffffffffu, accB[mt], 2);
        }
        if (tig == 0) {
            #pragma unroll
            for (int mt = 0; mt < 2; mt++) {
                sm[SCW + (m0 + mt * 16 + gid) * 4 + (wid >> 2)]     = accA[mt];
                sm[SCW + (m0 + mt * 16 + gid + 8) * 4 + (wid >> 2)] = accB[mt];
            }
        }
        __syncthreads();

        if (tid < 128) {
            float c = sm[SCW + tid * 4] + sm[SCW + tid * 4 + 1]
                    + sm[SCW + tid * 4 + 2] + sm[SCW + tid * 4 + 3] + bx2v;
            int d = sDst[tid];
            atomicAdd(&g_num[d * 3 + 0], sm[SREL + tid * 4 + 0] * c);
            atomicAdd(&g_num[d * 3 + 1], sm[SREL + tid * 4 + 1] * c);
            atomicAdd(&g_num[d * 3 + 2], sm[SREL + tid * 4 + 2] * c);
            atomicAdd(&g_cnt[d], 1.f);
        }
    }
}

// -------- kernel 3: x update --------
__global__ void k_xupd(const float* __restrict__ x, float* __restrict__ x_out) {
    int i = blockIdx.x * blockDim.x + threadIdx.x;
    if (i < Nn) {
        float inv = __frcp_rn(fmaxf(g_cnt[i], 1.f));
        x_out[i * 3 + 0] = x[i * 3 + 0] + g_num[i * 3 + 0] * inv;
        x_out[i * 3 + 1] = x[i * 3 + 1] + g_num[i * 3 + 1] * inv;
        x_out[i * 3 + 2] = x[i * 3 + 2] + g_num[i * 3 + 2] * inv;
    }
}

// -------- kernel 4: g_G = silu([h|agg] @ Wh1 + bh1) --------
__global__ __launch_bounds__(512, 1) void k_h1(const float* __restrict__ h,
                                               const float* __restrict__ Wh1,
                                               const float* __restrict__ bh1) {
    extern __shared__ __align__(16) float sm[];
    uint32_t* smu = (uint32_t*)sm;
    const int tid = threadIdx.x, wid = tid >> 5, lane = tid & 31;
    const int gid = lane >> 2, tig = lane & 3;
    const int row0 = blockIdx.x * 128;

    for (int i = tid; i < 16384; i += 512) {
        int k = i >> 7, n = i & 127;
        smu[NB1 + n * 132 + k] = f2tf32(Wh1[i]);
        smu[NB2 + n * 132 + k] = f2tf32(Wh1[16384 + i]);
    }
    load_a_tile(smu + NA, h, row0, tid);
    __syncthreads();

    const int m0 = (wid & 3) * 32, n0 = (wid >> 2) * 32;
    float C[8][4] = {};
    warp_gemm32(smu + NA, smu + NB1, C, m0, n0, gid, tig);
    __syncthreads();
    load_a_tile(smu + NA, g_agg, row0, tid);
    __syncthreads();
    warp_gemm32(smu + NA, smu + NB2, C, m0, n0, gid, tig);

    #pragma unroll
    for (int mt = 0; mt < 2; mt++) {
        const int ra = m0 + mt * 16 + gid, rb = ra + 8;
        #pragma unroll
        for (int nt = 0; nt < 4; nt++) {
            const int col = n0 + nt * 8 + tig * 2;
            float* c = C[mt * 4 + nt];
            float b0 = bh1[col], b1 = bh1[col + 1];
            if (row0 + ra < Nn)
                *(float2*)(g_G + (size_t)(row0 + ra) * 128 + col) =
                    make_float2(silu_f(c[0] + b0), silu_f(c[1] + b1));
            if (row0 + rb < Nn)
                *(float2*)(g_G + (size_t)(row0 + rb) * 128 + col) =
                    make_float2(silu_f(c[2] + b0), silu_f(c[3] + b1));
        }
    }
}

// -------- kernel 5: h_out = LN(h + g_G @ Wh2 + bh2) --------
__global__ __launch_bounds__(512, 1) void k_h2(const float* __restrict__ h,
                                               const float* __restrict__ Wh2,
                                               const float* __restrict__ bh2,
                                               const float* __restrict__ gamma,
                                               const float* __restrict__ beta,
                                               float* __restrict__ h_out) {
    extern __shared__ __align__(16) float sm[];
    uint32_t* smu = (uint32_t*)sm;
    const int tid = threadIdx.x, wid = tid >> 5, lane = tid & 31;
    const int gid = lane >> 2, tig = lane & 3;
    const int row0 = blockIdx.x * 128;
    const int SBo = 0, SAo = 16896;

    for (int i = tid; i < 16384; i += 512) {
        int k = i >> 7, n = i & 127;
        smu[SBo + n * 132 + k] = f2tf32(Wh2[i]);
    }
    load_a_tile(smu + SAo, g_G, row0, tid);
    __syncthreads();

    const int m0 = (wid & 3) * 32, n0 = (wid >> 2) * 32;
    float C[8][4] = {};
    warp_gemm32(smu + SAo, smu + SBo, C, m0, n0, gid, tig);
    __syncthreads();

    // v = C + bh2 -> sA (fp32)
    #pragma unroll
    for (int mt = 0; mt < 2; mt++) {
        const int ra = m0 + mt * 16 + gid, rb = ra + 8;
        #pragma unroll
        for (int nt = 0; nt < 4; nt++) {
            const int col = n0 + nt * 8 + tig * 2;
            float* c = C[mt * 4 + nt];
            float b0 = bh2[col], b1 = bh2[col + 1];
            sm[SAo + ra * 132 + col]     = c[0] + b0;
            sm[SAo + ra * 132 + col + 1] = c[1] + b1;
            sm[SAo + rb * 132 + col]     = c[2] + b0;
            sm[SAo + rb * 132 + col + 1] = c[3] + b1;
        }
    }
    __syncthreads();

    // LN pass: 4 rows/thread, 8 cols, 16-lane shuffle per row
    const int tx = tid & 15, ty = tid >> 4;
    const int r0 = ty * 4, c0 = tx * 8;
    #pragma unroll
    for (int i = 0; i < 4; i++) {
        int r = r0 + i, gr = row0 + r;
        float v[8];
        float4 h0 = make_float4(0.f, 0.f, 0.f, 0.f), h1 = h0;
        if (gr < Nn) {
            h0 = *(const float4*)(h + (size_t)gr * 128 + c0);
            h1 = *(const float4*)(h + (size_t)gr * 128 + c0 + 4);
        }
        v[0] = h0.x + sm[SAo + r * 132 + c0 + 0];
        v[1] = h0.y + sm[SAo + r * 132 + c0 + 1];
        v[2] = h0.z + sm[SAo + r * 132 + c0 + 2];
        v[3] = h0.w + sm[SAo + r * 132 + c0 + 3];
        v[4] = h1.x + sm[SAo + r * 132 + c0 + 4];
        v[5] = h1.y + sm[SAo + r * 132 + c0 + 5];
        v[6] = h1.z + sm[SAo + r * 132 + c0 + 6];
        v[7] = h1.w + sm[SAo + r * 132 + c0 + 7];
        float s1 = 0.f, s2 = 0.f;
        #pragma unroll
        for (int j = 0; j < 8; j++) { s1 += v[j]; s2 = fmaf(v[j], v[j], s2); }
        #pragma unroll
        for (int msk = 1; msk < 16; msk <<= 1) {
            s1 += __shfl_xor_sync(0xffffffffu, s1, msk);
            s2 += __shfl_xor_sync(0xffffffffu, s2, msk);
        }
        float mu = s1 * (1.f / 128.f);
        float var = s2 * (1.f / 128.f) - mu * mu;
        float rs = rsqrtf(var + LN_EPS);
        if (gr < Nn) {
            #pragma unroll
            for (int j = 0; j < 8; j++)
                h_out[(size_t)gr * 128 + c0 + j] =
                    (v[j] - mu) * rs * gamma[c0 + j] + beta[c0 + j];
        }
    }
}

// -------- launch --------
extern "C" void kernel_launch(void* const* d_in, const int* in_sizes, int n_in,
                              void* d_out, int out_size) {
    const float* h    = (const float*)d_in[0];
    const float* x    = (const float*)d_in[1];
    const float* vel  = (const float*)d_in[2];
    const void*  ei   = d_in[3];
    const float* We1  = (const float*)d_in[4];
    const float* be1  = (const float*)d_in[5];
    const float* We2  = (const float*)d_in[6];
    const float* be2  = (const float*)d_in[7];
    const float* Wx1  = (const float*)d_in[8];
    const float* bx1  = (const float*)d_in[9];
    const float* Wx2  = (const float*)d_in[10];
    const float* bx2  = (const float*)d_in[11];
    const float* Wh1  = (const float*)d_in[12];
    const float* bh1  = (const float*)d_in[13];
    const float* Wh2  = (const float*)d_in[14];
    const float* bh2  = (const float*)d_in[15];
    const float* gam  = (const float*)d_in[16];
    const float* bet  = (const float*)d_in[17];

    float* out_h = (float*)d_out;
    float* out_x = out_h + (size_t)Nn * 128;
    float* out_m = out_x + (size_t)Nn * 3;

    const int SM_E = SMT * 4;   // 221696 B

    int nsm = 148;
    cudaDeviceGetAttribute(&nsm, cudaDevAttrMultiProcessorCount, 0);

    cudaFuncSetAttribute(k_nodeprep, cudaFuncAttributeMaxDynamicSharedMemorySize, NSM);
    cudaFuncSetAttribute(k_edge,     cudaFuncAttributeMaxDynamicSharedMemorySize, SM_E);
    cudaFuncSetAttribute(k_h1,       cudaFuncAttributeMaxDynamicSharedMemorySize, NSM);
    cudaFuncSetAttribute(k_h2,       cudaFuncAttributeMaxDynamicSharedMemorySize, NSM2);

    k_zero<<<2048, 256>>>(ei);
    k_nodeprep<<<NT128, 512, NSM>>>(h, We1);
    k_edge<<<nsm, 512, SM_E>>>(x, vel, ei, We1, be1, We2, be2,
                               Wx1, bx1, Wx2, bx2, out_m);
    k_xupd<<<(Nn + 255) / 256, 256>>>(x, out_x);
    k_h1<<<NT128, 512, NSM>>>(h, Wh1, bh1);
    k_h2<<<NT128, 512, NSM2>>>(h, Wh2, bh2, gam, bet, out_h);
}

// round 11
// speedup vs baseline: 3.1730x; 1.3437x over previous
#include <cuda_runtime.h>
#include <cstdint>

#define Nn 50000
#define Ee 800000
#define NTILE 6250
#define NT128 391
#define LN_EPS 1e-5f

// -------- scratch --------
__device__ __align__(16) float g_PQ[(size_t)Nn * 256];
__device__ __align__(16) float g_agg[(size_t)Nn * 128];
__device__ __align__(16) float g_G[(size_t)Nn * 128];
__device__ float g_num[Nn * 3];
__device__ float g_cnt[Nn];
__device__ int   g_is64;

// silu via tanh (1 MUFU): v*sigmoid(v) = 0.5v + 0.5v*tanh(0.5v)
__device__ __forceinline__ float silu_f(float v) {
    float t;
    asm("tanh.approx.f32 %0, %1;" : "=f"(t) : "f"(0.5f * v));
    return fmaf(0.5f * v, t, 0.5f * v);
}
__device__ __forceinline__ int eidx(const void* p, long long i) {
    if (g_is64) return (int)((const long long*)p)[i];
    return ((const int*)p)[i];
}
__device__ __forceinline__ void red4(float* p, float a, float b, float c, float d) {
    asm volatile("red.global.add.v4.f32 [%0], {%1,%2,%3,%4};"
                 :: "l"(p), "f"(a), "f"(b), "f"(c), "f"(d) : "memory");
}
__device__ __forceinline__ uint32_t h2pack(float lo, float hi) {
    uint32_t r;
    asm("cvt.rn.f16x2.f32 %0, %1, %2;" : "=r"(r) : "f"(hi), "f"(lo));
    return r;
}
__device__ __forceinline__ float2 h2unpack(uint32_t u) {
    float2 f;
    asm("{.reg .b16 l, h;\n\t mov.b32 {l, h}, %2;\n\t"
        "cvt.f32.f16 %0, l;\n\t cvt.f32.f16 %1, h;}\n"
        : "=f"(f.x), "=f"(f.y) : "r"(u));
    return f;
}
__device__ __forceinline__ void mma_f16(float* c, const uint32_t* a, const uint32_t* b) {
    asm volatile("mma.sync.aligned.m16n8k16.row.col.f32.f16.f16.f32 "
        "{%0,%1,%2,%3}, {%4,%5,%6,%7}, {%8,%9}, {%0,%1,%2,%3};"
        : "+f"(c[0]), "+f"(c[1]), "+f"(c[2]), "+f"(c[3])
        : "r"(a[0]), "r"(a[1]), "r"(a[2]), "r"(a[3]), "r"(b[0]), "r"(b[1]));
}

// Swizzled fp16 tile: 128 rows x 64 half2 (128 halves). phys_u32(r,kk) = r*64 + (kk ^ (4*(r&7)))
// warp computes 64 rows x 32 cols: mt 0..3 (16-row steps), nt 0..3 (8-col steps)
__device__ __forceinline__ void warp_gemm64x32(const uint32_t* __restrict__ sA,
                                               const uint32_t* __restrict__ sB,
                                               float C[16][4],
                                               int m0, int n0, int gid, int tig) {
    const int sw = 4 * gid;
    #pragma unroll
    for (int ks = 0; ks < 8; ks++) {
        const int k0 = ks * 8;
        const int offA = (k0 + tig) ^ sw, offA4 = (k0 + tig + 4) ^ sw;
        uint32_t a[4][4], b[4][2];
        #pragma unroll
        for (int mt = 0; mt < 4; mt++) {
            const int r = m0 + mt * 16 + gid;
            a[mt][0] = sA[r * 64 + offA];
            a[mt][1] = sA[(r + 8) * 64 + offA];
            a[mt][2] = sA[r * 64 + offA4];
            a[mt][3] = sA[(r + 8) * 64 + offA4];
        }
        #pragma unroll
        for (int nt = 0; nt < 4; nt++) {
            const int n = n0 + nt * 8 + gid;
            b[nt][0] = sB[n * 64 + offA];
            b[nt][1] = sB[n * 64 + offA4];
        }
        #pragma unroll
        for (int mt = 0; mt < 4; mt++)
            #pragma unroll
            for (int nt = 0; nt < 4; nt++)
                mma_f16(C[mt * 4 + nt], a[mt], b[nt]);
    }
}

// load 128x128 fp32 gmem tile -> swizzled fp16 smem tile (256 threads)
__device__ __forceinline__ void load_a_f16(uint32_t* __restrict__ dst,
                                           const float* __restrict__ src,
                                           int row0, int tid) {
    const int r = tid >> 1, q = tid & 1, gr = row0 + r;
    #pragma unroll
    for (int j = 0; j < 8; j++) {
        const int ch = q * 8 + j;
        float4 v0 = make_float4(0.f, 0.f, 0.f, 0.f), v1 = v0;
        if (gr < Nn) {
            v0 = *(const float4*)(src + (size_t)gr * 128 + ch * 8);
            v1 = *(const float4*)(src + (size_t)gr * 128 + ch * 8 + 4);
        }
        uint4 u;
        u.x = h2pack(v0.x, v0.y); u.y = h2pack(v0.z, v0.w);
        u.z = h2pack(v1.x, v1.y); u.w = h2pack(v1.z, v1.w);
        ((uint4*)dst)[r * 16 + (ch ^ (r & 7))] = u;
    }
}

// load 128x128 fp32 weight W[k][n] -> swizzled fp16 [n][kk] tile (256 threads)
__device__ __forceinline__ void load_b_f16(uint32_t* __restrict__ dst,
                                           const float* __restrict__ W, int tid) {
    for (int i = tid; i < 2048; i += 256) {
        const int kk = i >> 5, n4 = (i & 31) * 4;
        float4 a0 = *(const float4*)(W + (2 * kk) * 128 + n4);
        float4 a1 = *(const float4*)(W + (2 * kk + 1) * 128 + n4);
        dst[(n4 + 0) * 64 + (kk ^ (4 * ((n4 + 0) & 7)))] = h2pack(a0.x, a1.x);
        dst[(n4 + 1) * 64 + (kk ^ (4 * ((n4 + 1) & 7)))] = h2pack(a0.y, a1.y);
        dst[(n4 + 2) * 64 + (kk ^ (4 * ((n4 + 2) & 7)))] = h2pack(a0.z, a1.z);
        dst[(n4 + 3) * 64 + (kk ^ (4 * ((n4 + 3) & 7)))] = h2pack(a0.w, a1.w);
    }
}

// -------- kernel 0: zero scratch + dtype detect --------
__global__ void k_zero(const void* __restrict__ ei) {
    if (blockIdx.x == 0 && threadIdx.x == 0) {
        const int* w = (const int*)ei;
        int all0 = 1;
        #pragma unroll 1
        for (int i = 0; i < 64; i++) if (w[2 * i + 1] != 0) all0 = 0;
        g_is64 = all0;
    }
    size_t i = (size_t)blockIdx.x * blockDim.x + threadIdx.x;
    size_t stride = (size_t)gridDim.x * blockDim.x;
    for (size_t j = i; j < (size_t)Nn * 128; j += stride) g_agg[j] = 0.f;
    for (size_t j = i; j < (size_t)Nn * 3;   j += stride) g_num[j] = 0.f;
    for (size_t j = i; j < (size_t)Nn;       j += stride) g_cnt[j] = 0.f;
}

// ===== node kernels: 256 threads, 8 warps, fp16 mma =====
#define NB1 0
#define NB2 8192
#define NA  16384
#define NPART 16384            // k_h2: partials after HA at 8192.. (HB at 0, HA 8192)
#define NSM3 ((16384 + 8192) * 4)   // 98304 B
#define NSMH ((8192 * 2 + 1024) * 4) // 69632 B (k_h2)

// -------- kernel 1: [P|Q] = h @ We1[0:128], h @ We1[128:256] --------
__global__ __launch_bounds__(256, 2) void k_nodeprep(const float* __restrict__ h,
                                                     const float* __restrict__ We1) {
    extern __shared__ __align__(16) uint32_t smu[];
    const int tid = threadIdx.x, wid = tid >> 5, lane = tid & 31;
    const int gid = lane >> 2, tig = lane & 3;
    const int row0 = blockIdx.x * 128;
    const int m0 = (wid & 1) * 64, n0 = (wid >> 1) * 32;

    load_b_f16(smu + NB1, We1, tid);
    load_b_f16(smu + NB2, We1 + 16384, tid);
    load_a_f16(smu + NA, h, row0, tid);
    __syncthreads();

    #pragma unroll 1
    for (int half = 0; half < 2; half++) {
        float C[16][4] = {};
        warp_gemm64x32(smu + NA, smu + (half ? NB2 : NB1), C, m0, n0, gid, tig);
        #pragma unroll
        for (int mt = 0; mt < 4; mt++) {
            const int ra = m0 + mt * 16 + gid, rb = ra + 8;
            #pragma unroll
            for (int nt = 0; nt < 4; nt++) {
                const int col = n0 + nt * 8 + tig * 2;
                float* c = C[mt * 4 + nt];
                if (row0 + ra < Nn)
                    *(float2*)(g_PQ + (size_t)(row0 + ra) * 256 + half * 128 + col) =
                        make_float2(c[0], c[1]);
                if (row0 + rb < Nn)
                    *(float2*)(g_PQ + (size_t)(row0 + rb) * 256 + half * 128 + col) =
                        make_float2(c[2], c[3]);
            }
        }
    }
}

// -------- kernel 2: persistent fused edge pipeline (fp16 mma, 256 thr, 2 CTA/SM) --------
// u32 offsets
#define HB1  0       // We2 [n][kk] 8192
#define HB2  8192    // Wx1
#define HA   16384   // A tile 8192
#define HW1G 24576   // fp16 [11][64] 704
#define SBE1 25280
#define SBE2 25408
#define SBX1 25536
#define SWX2 25664
#define SGEO 25792   // fp16 [128][6 u32] 768
#define SREL 26560   // fp32 [128][4] 512
#define SSRC 27072
#define SDST 27200
#define SCW  27328   // [128][4] 512
#define SMT  27840   // -> 111360 B

__global__ __launch_bounds__(256, 2) void k_edge(
    const float* __restrict__ x, const float* __restrict__ vel,
    const void* __restrict__ ei,
    const float* __restrict__ We1, const float* __restrict__ be1,
    const float* __restrict__ We2, const float* __restrict__ be2,
    const float* __restrict__ Wx1, const float* __restrict__ bx1,
    const float* __restrict__ Wx2, const float* __restrict__ bx2,
    float* __restrict__ m_out)
{
    extern __shared__ __align__(16) uint32_t smu[];
    float* sm = (float*)smu;
    const int tid = threadIdx.x, wid = tid >> 5, lane = tid & 31;
    const int gid = lane >> 2, tig = lane & 3;
    int* sSrc = (int*)&smu[SSRC];
    int* sDst = (int*)&smu[SDST];

    load_b_f16(smu + HB1, We2, tid);
    load_b_f16(smu + HB2, Wx1, tid);
    for (int i = tid; i < 704; i += 256) {
        int g = i >> 6, kk = i & 63;
        smu[HW1G + i] = h2pack(We1[32768 + g * 128 + 2 * kk],
                               We1[32768 + g * 128 + 2 * kk + 1]);
    }
    if (tid < 128) { sm[SBE1 + tid] = be1[tid]; sm[SBE2 + tid] = be2[tid];
                     sm[SBX1 + tid] = bx1[tid]; sm[SWX2 + tid] = Wx2[tid]; }
    const float bx2v = bx2[0];

    const int tx = tid & 15, ty = tid >> 4;          // t-build: 8 rows, 8 cols each
    const int c0 = tx * 8;
    const int m0 = (wid & 1) * 64, n0 = (wid >> 1) * 32, ng = wid >> 1;
    const int n0h = n0 >> 1;
    const int drow = tid >> 1, dq = tid & 1;         // dump: 2 threads/row

    for (long long tile = blockIdx.x; tile < NTILE; tile += gridDim.x) {
        const long long e0 = tile * 128;
        __syncthreads();

        // geometry
        if (tid < 128) {
            int e = tid;
            int s = eidx(ei, e0 + e), d = eidx(ei, (long long)Ee + e0 + e);
            sSrc[e] = s; sDst[e] = d;
            float rx = x[s * 3 + 0] - x[d * 3 + 0];
            float ry = x[s * 3 + 1] - x[d * 3 + 1];
            float rz = x[s * 3 + 2] - x[d * 3 + 2];
            float d2 = rx * rx + ry * ry + rz * rz;
            float inv = __frcp_rn(fmaxf(sqrtf(d2), 1e-8f));
            float hx = rx * inv, hy = ry * inv, hz = rz * inv;
            sm[SREL + e * 4 + 0] = rx; sm[SREL + e * 4 + 1] = ry; sm[SREL + e * 4 + 2] = rz;
            float gv[12];
            gv[0] = d2;
            #pragma unroll
            for (int i = 0; i < 5; i++) {
                const float* vs = vel + ((size_t)s * 5 + i) * 3;
                gv[1 + i] = vs[0] * hx + vs[1] * hy + vs[2] * hz;
            }
            #pragma unroll
            for (int i = 0; i < 5; i++) {
                const float* vd = vel + ((size_t)d * 5 + i) * 3;
                gv[6 + i] = vd[0] * hx + vd[1] * hy + vd[2] * hz;
            }
            gv[11] = 0.f;
            #pragma unroll
            for (int p = 0; p < 6; p++)
                smu[SGEO + e * 6 + p] = h2pack(gv[2 * p], gv[2 * p + 1]);
        }
        __syncthreads();

        // t = silu(P[src]+Q[dst]+geom@W1g+be1) -> HA (fp16 swizzled)
        #pragma unroll 1
        for (int rr = 0; rr < 8; rr++) {
            const int e = ty * 8 + rr;
            const int s = sSrc[e], d = sDst[e];
            const float* prow = g_PQ + (size_t)s * 256 + c0;
            const float* qrow = g_PQ + (size_t)d * 256 + 128 + c0;
            float4 p0 = *(const float4*)prow,  p1 = *(const float4*)(prow + 4);
            float4 q0 = *(const float4*)qrow,  q1 = *(const float4*)(qrow + 4);
            float t[8];
            t[0] = p0.x + q0.x; t[1] = p0.y + q0.y; t[2] = p0.z + q0.z; t[3] = p0.w + q0.w;
            t[4] = p1.x + q1.x; t[5] = p1.y + q1.y; t[6] = p1.z + q1.z; t[7] = p1.w + q1.w;
            #pragma unroll
            for (int j = 0; j < 8; j++) t[j] += sm[SBE1 + c0 + j];
            float gv[12];
            #pragma unroll
            for (int p = 0; p < 6; p++) {
                float2 f = h2unpack(smu[SGEO + e * 6 + p]);
                gv[2 * p] = f.x; gv[2 * p + 1] = f.y;
            }
            #pragma unroll
            for (int g = 0; g < 11; g++) {
                #pragma unroll
                for (int jj = 0; jj < 4; jj++) {
                    float2 w = h2unpack(smu[HW1G + g * 64 + tx * 4 + jj]);
                    t[2 * jj]     = fmaf(gv[g], w.x, t[2 * jj]);
                    t[2 * jj + 1] = fmaf(gv[g], w.y, t[2 * jj + 1]);
                }
            }
            uint4 u;
            u.x = h2pack(silu_f(t[0]), silu_f(t[1]));
            u.y = h2pack(silu_f(t[2]), silu_f(t[3]));
            u.z = h2pack(silu_f(t[4]), silu_f(t[5]));
            u.w = h2pack(silu_f(t[6]), silu_f(t[7]));
            ((uint4*)(smu + HA))[e * 16 + (tx ^ (e & 7))] = u;
        }
        __syncthreads();

        // GEMM1: C = t @ We2
        float C[16][4] = {};
        warp_gemm64x32(smu + HA, smu + HB1, C, m0, n0, gid, tig);
        __syncthreads();

        // epilogue1: m = silu(C + be2) -> HA (fp16)
        #pragma unroll
        for (int mt = 0; mt < 4; mt++) {
            const int ra = m0 + mt * 16 + gid, rb = ra + 8;
            const int swa = 4 * (ra & 7);
            #pragma unroll
            for (int nt = 0; nt < 4; nt++) {
                const int col = n0 + nt * 8 + tig * 2;
                const int kk = n0h + nt * 4 + tig;
                float* c = C[mt * 4 + nt];
                float b0 = sm[SBE2 + col], b1 = sm[SBE2 + col + 1];
                smu[HA + ra * 64 + (kk ^ swa)] = h2pack(silu_f(c[0] + b0), silu_f(c[1] + b1));
                smu[HA + rb * 64 + (kk ^ swa)] = h2pack(silu_f(c[2] + b0), silu_f(c[3] + b1));
            }
        }
        __syncthreads();

        // GEMM2: C = m @ Wx1 ; concurrently dump m -> m_out + agg
        #pragma unroll
        for (int i = 0; i < 16; i++)
            { C[i][0] = 0.f; C[i][1] = 0.f; C[i][2] = 0.f; C[i][3] = 0.f; }
        warp_gemm64x32(smu + HA, smu + HB2, C, m0, n0, gid, tig);

        {
            const int da = sDst[drow];
            float* go = m_out + (size_t)(e0 + drow) * 128;
            float* ga = g_agg + (size_t)da * 128;
            const int rsw = drow & 7;
            #pragma unroll
            for (int j = 0; j < 8; j++) {
                const int ch = dq * 8 + j;
                uint4 u = ((uint4*)(smu + HA))[drow * 16 + (ch ^ rsw)];
                float2 f0 = h2unpack(u.x), f1 = h2unpack(u.y);
                float2 f2 = h2unpack(u.z), f3 = h2unpack(u.w);
                *(float4*)(go + ch * 8)     = make_float4(f0.x, f0.y, f1.x, f1.y);
                *(float4*)(go + ch * 8 + 4) = make_float4(f2.x, f2.y, f3.x, f3.y);
                red4(ga + ch * 8,     f0.x, f0.y, f1.x, f1.y);
                red4(ga + ch * 8 + 4, f2.x, f2.y, f3.x, f3.y);
            }
        }

        // epilogue2: cw partials = sum over warp's 32 cols of silu(C+bx1)*Wx2
        float accA[4] = {}, accB[4] = {};
        #pragma unroll
        for (int mt = 0; mt < 4; mt++) {
            #pragma unroll
            for (int nt = 0; nt < 4; nt++) {
                const int col = n0 + nt * 8 + tig * 2;
                float* c = C[mt * 4 + nt];
                float w0 = sm[SWX2 + col], w1 = sm[SWX2 + col + 1];
                float b0 = sm[SBX1 + col], b1 = sm[SBX1 + col + 1];
                accA[mt] = fmaf(silu_f(c[0] + b0), w0, accA[mt]);
                accA[mt] = fmaf(silu_f(c[1] + b1), w1, accA[mt]);
                accB[mt] = fmaf(silu_f(c[2] + b0), w0, accB[mt]);
                accB[mt] = fmaf(silu_f(c[3] + b1), w1, accB[mt]);
            }
        }
        #pragma unroll
        for (int mt = 0; mt < 4; mt++) {
            accA[mt] += __shfl_xor_sync(0xffffffffu, accA[mt], 1);
            accA[mt] += __shfl_xor_sync(0xffffffffu, accA[mt], 2);
            accB[mt] += __shfl_xor_sync(0xffffffffu, accB[mt], 1);
            accB[mt] += __shfl_xor_sync(0xffffffffu, accB[mt], 2);
        }
        if (tig == 0) {
            #pragma unroll
            for (int mt = 0; mt < 4; mt++) {
                sm[SCW + (m0 + mt * 16 + gid) * 4 + ng]     = accA[mt];
                sm[SCW + (m0 + mt * 16 + gid + 8) * 4 + ng] = accB[mt];
            }
        }
        __syncthreads();

        if (tid < 128) {
            float c = sm[SCW + tid * 4] + sm[SCW + tid * 4 + 1]
                    + sm[SCW + tid * 4 + 2] + sm[SCW + tid * 4 + 3] + bx2v;
            int d = sDst[tid];
            atomicAdd(&g_num[d * 3 + 0], sm[SREL + tid * 4 + 0] * c);
            atomicAdd(&g_num[d * 3 + 1], sm[SREL + tid * 4 + 1] * c);
            atomicAdd(&g_num[d * 3 + 2], sm[SREL + tid * 4 + 2] * c);
            atomicAdd(&g_cnt[d], 1.f);
        }
    }
}

// -------- kernel 3: x update --------
__global__ void k_xupd(const float* __restrict__ x, float* __restrict__ x_out) {
    int i = blockIdx.x * blockDim.x + threadIdx.x;
    if (i < Nn) {
        float inv = __frcp_rn(fmaxf(g_cnt[i], 1.f));
        x_out[i * 3 + 0] = x[i * 3 + 0] + g_num[i * 3 + 0] * inv;
        x_out[i * 3 + 1] = x[i * 3 + 1] + g_num[i * 3 + 1] * inv;
        x_out[i * 3 + 2] = x[i * 3 + 2] + g_num[i * 3 + 2] * inv;
    }
}

// -------- kernel 4: g_G = silu([h|agg] @ Wh1 + bh1) --------
__global__ __launch_bounds__(256, 2) void k_h1(const float* __restrict__ h,
                                               const float* __restrict__ Wh1,
                                               const float* __restrict__ bh1) {
    extern __shared__ __align__(16) uint32_t smu[];
    const int tid = threadIdx.x, wid = tid >> 5, lane = tid & 31;
    const int gid = lane >> 2, tig = lane & 3;
    const int row0 = blockIdx.x * 128;
    const int m0 = (wid & 1) * 64, n0 = (wid >> 1) * 32;

    load_b_f16(smu + NB1, Wh1, tid);
    load_b_f16(smu + NB2, Wh1 + 16384, tid);
    load_a_f16(smu + NA, h, row0, tid);
    __syncthreads();

    float C[16][4] = {};
    warp_gemm64x32(smu + NA, smu + NB1, C, m0, n0, gid, tig);
    __syncthreads();
    load_a_f16(smu + NA, g_agg, row0, tid);
    __syncthreads();
    warp_gemm64x32(smu + NA, smu + NB2, C, m0, n0, gid, tig);

    #pragma unroll
    for (int mt = 0; mt < 4; mt++) {
        const int ra = m0 + mt * 16 + gid, rb = ra + 8;
        #pragma unroll
        for (int nt = 0; nt < 4; nt++) {
            const int col = n0 + nt * 8 + tig * 2;
            float* c = C[mt * 4 + nt];
            float b0 = bh1[col], b1 = bh1[col + 1];
            if (row0 + ra < Nn)
                *(float2*)(g_G + (size_t)(row0 + ra) * 128 + col) =
                    make_float2(silu_f(c[0] + b0), silu_f(c[1] + b1));
            if (row0 + rb < Nn)
                *(float2*)(g_G + (size_t)(row0 + rb) * 128 + col) =
                    make_float2(silu_f(c[2] + b0), silu_f(c[3] + b1));
        }
    }
}

// -------- kernel 5: h_out = LN(h + g_G @ Wh2 + bh2) --------
__global__ __launch_bounds__(256, 2) void k_h2(const float* __restrict__ h,
                                               const float* __restrict__ Wh2,
                                               const float* __restrict__ bh2,
                                               const float* __restrict__ gamma,
                                               const float* __restrict__ beta,
                                               float* __restrict__ h_out) {
    extern __shared__ __align__(16) uint32_t smu[];
    float* sp = (float*)(smu + NPART);
    const int tid = threadIdx.x, wid = tid >> 5, lane = tid & 31;
    const int gid = lane >> 2, tig = lane & 3;
    const int row0 = blockIdx.x * 128;
    const int m0 = (wid & 1) * 64, n0 = (wid >> 1) * 32, ng = wid >> 1;

    load_b_f16(smu + 0, Wh2, tid);
    load_a_f16(smu + 8192, g_G, row0, tid);
    __syncthreads();

    float C[16][4] = {};
    warp_gemm64x32(smu + 8192, smu + 0, C, m0, n0, gid, tig);

    // v = C + bh2 + h ; per-row partial sums
    float s1a[4] = {}, s2a[4] = {}, s1b[4] = {}, s2b[4] = {};
    #pragma unroll
    for (int mt = 0; mt < 4; mt++) {
        const int gra = row0 + m0 + mt * 16 + gid, grb = gra + 8;
        #pragma unroll
        for (int nt = 0; nt < 4; nt++) {
            const int col = n0 + nt * 8 + tig * 2;
            float* c = C[mt * 4 + nt];
            float b0 = bh2[col], b1 = bh2[col + 1];
            float2 ha = make_float2(0.f, 0.f), hb = ha;
            if (gra < Nn) ha = *(const float2*)(h + (size_t)gra * 128 + col);
            if (grb < Nn) hb = *(const float2*)(h + (size_t)grb * 128 + col);
            c[0] += b0 + ha.x; c[1] += b1 + ha.y;
            c[2] += b0 + hb.x; c[3] += b1 + hb.y;
            s1a[mt] += c[0] + c[1]; s2a[mt] += c[0] * c[0] + c[1] * c[1];
            s1b[mt] += c[2] + c[3]; s2b[mt] += c[2] * c[2] + c[3] * c[3];
        }
    }
    #pragma unroll
    for (int mt = 0; mt < 4; mt++) {
        #pragma unroll
        for (int msk = 1; msk < 4; msk <<= 1) {
            s1a[mt] += __shfl_xor_sync(0xffffffffu, s1a[mt], msk);
            s2a[mt] += __shfl_xor_sync(0xffffffffu, s2a[mt], msk);
            s1b[mt] += __shfl_xor_sync(0xffffffffu, s1b[mt], msk);
            s2b[mt] += __shfl_xor_sync(0xffffffffu, s2b[mt], msk);
        }
    }
    if (tig == 0) {
        #pragma unroll
        for (int mt = 0; mt < 4; mt++) {
            const int ra = m0 + mt * 16 + gid, rb = ra + 8;
            sp[ra * 8 + ng * 2] = s1a[mt]; sp[ra * 8 + ng * 2 + 1] = s2a[mt];
            sp[rb * 8 + ng * 2] = s1b[mt]; sp[rb * 8 + ng * 2 + 1] = s2b[mt];
        }
    }
    __syncthreads();

    #pragma unroll
    for (int mt = 0; mt < 4; mt++) {
        const int ra = m0 + mt * 16 + gid, rb = ra + 8;
        float s1 = sp[ra * 8] + sp[ra * 8 + 2] + sp[ra * 8 + 4] + sp[ra * 8 + 6];
        float s2 = sp[ra * 8 + 1] + sp[ra * 8 + 3] + sp[ra * 8 + 5] + sp[ra * 8 + 7];
        float mua = s1 * (1.f / 128.f);
        float rsa = rsqrtf(s2 * (1.f / 128.f) - mua * mua + LN_EPS);
        s1 = sp[rb * 8] + sp[rb * 8 + 2] + sp[rb * 8 + 4] + sp[rb * 8 + 6];
        s2 = sp[rb * 8 + 1] + sp[rb * 8 + 3] + sp[rb * 8 + 5] + sp[rb * 8 + 7];
        float mub = s1 * (1.f / 128.f);
        float rsb = rsqrtf(s2 * (1.f / 128.f) - mub * mub + LN_EPS);
        const int gra = row0 + ra, grb = row0 + rb;
        #pragma unroll
        for (int nt = 0; nt < 4; nt++) {
            const int col = n0 + nt * 8 + tig * 2;
            float* c = C[mt * 4 + nt];
            float gm0 = gamma[col], gm1 = gamma[col + 1];
            float bt0 = beta[col],  bt1 = beta[col + 1];
            if (gra < Nn)
                *(float2*)(h_out + (size_t)gra * 128 + col) =
                    make_float2((c[0] - mua) * rsa * gm0 + bt0,
                                (c[1] - mua) * rsa * gm1 + bt1);
            if (grb < Nn)
                *(float2*)(h_out + (size_t)grb * 128 + col) =
                    make_float2((c[2] - mub) * rsb * gm0 + bt0,
                                (c[3] - mub) * rsb * gm1 + bt1);
        }
    }
}

// -------- launch --------
extern "C" void kernel_launch(void* const* d_in, const int* in_sizes, int n_in,
                              void* d_out, int out_size) {
    const float* h    = (const float*)d_in[0];
    const float* x    = (const float*)d_in[1];
    const float* vel  = (const float*)d_in[2];
    const void*  ei   = d_in[3];
    const float* We1  = (const float*)d_in[4];
    const float* be1  = (const float*)d_in[5];
    const float* We2  = (const float*)d_in[6];
    const float* be2  = (const float*)d_in[7];
    const float* Wx1  = (const float*)d_in[8];
    const float* bx1  = (const float*)d_in[9];
    const float* Wx2  = (const float*)d_in[10];
    const float* bx2  = (const float*)d_in[11];
    const float* Wh1  = (const float*)d_in[12];
    const float* bh1  = (const float*)d_in[13];
    const float* Wh2  = (const float*)d_in[14];
    const float* bh2  = (const float*)d_in[15];
    const float* gam  = (const float*)d_in[16];
    const float* bet  = (const float*)d_in[17];

    float* out_h = (float*)d_out;
    float* out_x = out_h + (size_t)Nn * 128;
    float* out_m = out_x + (size_t)Nn * 3;

    const int SM_E = SMT * 4;   // 111360 B

    int nsm = 148;
    cudaDeviceGetAttribute(&nsm, cudaDevAttrMultiProcessorCount, 0);

    cudaFuncSetAttribute(k_nodeprep, cudaFuncAttributeMaxDynamicSharedMemorySize, NSM3);
    cudaFuncSetAttribute(k_edge,     cudaFuncAttributeMaxDynamicSharedMemorySize, SM_E);
    cudaFuncSetAttribute(k_h1,       cudaFuncAttributeMaxDynamicSharedMemorySize, NSM3);
    cudaFuncSetAttribute(k_h2,       cudaFuncAttributeMaxDynamicSharedMemorySize, NSMH);

    k_zero<<<2048, 256>>>(ei);
    k_nodeprep<<<NT128, 256, NSM3>>>(h, We1);
    k_edge<<<nsm * 2, 256, SM_E>>>(x, vel, ei, We1, be1, We2, be2,
                                   Wx1, bx1, Wx2, bx2, out_m);
    k_xupd<<<(Nn + 255) / 256, 256>>>(x, out_x);
    k_h1<<<NT128, 256, NSM3>>>(h, Wh1, bh1);
    k_h2<<<NT128, 256, NSMH>>>(h, Wh2, bh2, gam, bet, out_h);
}